// round 8
// baseline (speedup 1.0000x reference)
#include <cuda_runtime.h>
#include <cstdint>

// Problem constants
#define Bb   2
#define Ss   2048
#define Hh   1024
#define NHh  16
#define HDd  64
#define Mrows (Bb*Ss)   // 4096

// ---------------------------------------------------------------------------
// Device scratch (no allocations allowed). All tf32 payloads stored as u32 bits.
// ---------------------------------------------------------------------------
__device__ uint32_t g_xt[Mrows*Hh];        // X in tf32
__device__ uint32_t g_wt[4*Hh*Hh];         // Wq,Wk,Wv,Wo in tf32
__device__ uint32_t g_qt[Bb*NHh*Ss*HDd];   // Q (pre-scaled by 1/8), tf32, [b,h,s,d]
__device__ uint32_t g_kt[Bb*NHh*Ss*HDd];   // K tf32
__device__ uint32_t g_vt[Bb*NHh*Ss*HDd];   // V tf32
__device__ uint32_t g_ctxt[Bb*Ss*Hh];      // attention output, tf32, [b,s,h]

__device__ __forceinline__ uint32_t f2tf32(float x) {
    uint32_t r;
    asm("cvt.rna.tf32.f32 %0, %1;" : "=r"(r) : "f"(x));
    return r;
}

__device__ __forceinline__ void mma_tf32(float d[4], const uint32_t a[4],
                                         const uint32_t b[2], const float c[4]) {
    asm volatile(
        "mma.sync.aligned.m16n8k8.row.col.f32.tf32.tf32.f32 "
        "{%0,%1,%2,%3}, {%4,%5,%6,%7}, {%8,%9}, {%10,%11,%12,%13};\n"
        : "=f"(d[0]), "=f"(d[1]), "=f"(d[2]), "=f"(d[3])
        : "r"(a[0]), "r"(a[1]), "r"(a[2]), "r"(a[3]),
          "r"(b[0]), "r"(b[1]),
          "f"(c[0]), "f"(c[1]), "f"(c[2]), "f"(c[3]));
}

__device__ __forceinline__ void cp_async16(uint32_t smem_addr, const void* gptr) {
    asm volatile("cp.async.cg.shared.global [%0], [%1], 16;\n"
                 :: "r"(smem_addr), "l"(gptr));
}
__device__ __forceinline__ uint32_t s2u(const void* p) {
    return (uint32_t)__cvta_generic_to_shared(p);
}

// ---------------------------------------------------------------------------
// Prologue: convert X and the 4 weight matrices to tf32 once.
// ---------------------------------------------------------------------------
__global__ __launch_bounds__(256)
void preconv(const float* __restrict__ x,
             const float* __restrict__ wq, const float* __restrict__ wk,
             const float* __restrict__ wv, const float* __restrict__ wo)
{
    const int i = blockIdx.x * blockDim.x + threadIdx.x;
    const int NX4 = (Mrows * Hh) / 4;   // 1,048,576
    const int NW4 = (Hh * Hh) / 4;      // 262,144

    if (i < NX4) {
        float4 v = ((const float4*)x)[i];
        uint4 u;
        u.x = f2tf32(v.x); u.y = f2tf32(v.y);
        u.z = f2tf32(v.z); u.w = f2tf32(v.w);
        ((uint4*)g_xt)[i] = u;
    }
    if (i < NW4) {
        const float* ws[4] = {wq, wk, wv, wo};
#pragma unroll
        for (int z = 0; z < 4; z++) {
            float4 v = ((const float4*)ws[z])[i];
            uint4 u;
            u.x = f2tf32(v.x); u.y = f2tf32(v.y);
            u.z = f2tf32(v.z); u.w = f2tf32(v.w);
            ((uint4*)(g_wt + (size_t)z * Hh * Hh))[i] = u;
        }
    }
}

// ---------------------------------------------------------------------------
// tf32 GEMM with cp.async 2-stage pipeline (round-6 config: 128 threads,
// 4 warps 2m x 2n, warp tile 64x64 — measured best).
// CTA 128x128, BK=32. dst: 0 -> Yout fp32; 1/2/3 -> g_qt/kt/vt.
// Dynamic SMEM: 2 stages x (A 128x36 + B 128x36) u32 = 73728 bytes.
// ---------------------------------------------------------------------------
#define GEMM_STG   (2*128*36)                 // words per stage (A+B)
#define GEMM_SMEM  (2*GEMM_STG*4)             // bytes

__device__ __forceinline__
void gemm_load_stage(const uint32_t* __restrict__ A, const uint32_t* __restrict__ Bm,
                     uint32_t* dstA, int m0, int n0, int k0, int tid)
{
    uint32_t* dstB = dstA + 128*36;
#pragma unroll
    for (int j = 0; j < 8; j++) {
        const int id  = j * 128 + tid;     // 0..1023
        const int row = id >> 3;
        const int col = (id & 7) * 4;
        cp_async16(s2u(dstA + row*36 + col), A  + (size_t)(m0+row)*Hh + k0 + col);
        cp_async16(s2u(dstB + row*36 + col), Bm + (size_t)(n0+row)*Hh + k0 + col);
    }
}

__device__ __forceinline__
void gemm_tc_body(const uint32_t* __restrict__ A, const uint32_t* __restrict__ Bm,
                  const float* __restrict__ bias, float* __restrict__ Yout,
                  int dst, int bx, int by, uint32_t* smem)
{
    const int tid  = threadIdx.x;
    const int lane = tid & 31;
    const int wid  = tid >> 5;
    const int wm   = (wid & 1) * 64;
    const int wn   = (wid >> 1) * 64;
    const int m0   = by * 128;
    const int n0   = bx * 128;
    const int g    = lane >> 2;
    const int tg   = lane & 3;

    float acc[4][8][4];
#pragma unroll
    for (int mt = 0; mt < 4; mt++)
#pragma unroll
        for (int nt = 0; nt < 8; nt++)
#pragma unroll
            for (int r = 0; r < 4; r++) acc[mt][nt][r] = 0.f;

    gemm_load_stage(A, Bm, smem, m0, n0, 0, tid);
    asm volatile("cp.async.commit_group;\n");

    for (int kt = 0; kt < 32; kt++) {
        if (kt + 1 < 32) {
            gemm_load_stage(A, Bm, smem + ((kt+1)&1)*GEMM_STG, m0, n0, (kt+1)*32, tid);
            asm volatile("cp.async.commit_group;\n");
            asm volatile("cp.async.wait_group 1;\n");
        } else {
            asm volatile("cp.async.wait_group 0;\n");
        }
        __syncthreads();

        const uint32_t* As = smem + (kt & 1) * GEMM_STG;
        const uint32_t* Bs = As + 128*36;

#pragma unroll
        for (int kc = 0; kc < 32; kc += 8) {
            uint32_t af[4][4];
            uint32_t bf[8][2];
#pragma unroll
            for (int mt = 0; mt < 4; mt++) {
                const uint32_t* r0p = As + (wm + mt*16 + g)*36 + kc;
                af[mt][0] = r0p[tg];
                af[mt][2] = r0p[tg + 4];
                const uint32_t* r1p = r0p + 8*36;
                af[mt][1] = r1p[tg];
                af[mt][3] = r1p[tg + 4];
            }
#pragma unroll
            for (int nt = 0; nt < 8; nt++) {
                const uint32_t* cp_ = Bs + (wn + nt*8 + g)*36 + kc;
                bf[nt][0] = cp_[tg];
                bf[nt][1] = cp_[tg + 4];
            }
#pragma unroll
            for (int mt = 0; mt < 4; mt++)
#pragma unroll
                for (int nt = 0; nt < 8; nt++)
                    mma_tf32(acc[mt][nt], af[mt], bf[nt], acc[mt][nt]);
        }
        __syncthreads();
    }

    // epilogue
    const float qscale = (dst == 1) ? 0.125f : 1.0f;
#pragma unroll
    for (int mt = 0; mt < 4; mt++) {
#pragma unroll
        for (int nt = 0; nt < 8; nt++) {
            const int mA = m0 + wm + mt*16 + g;
            const int nA = n0 + wn + nt*8 + tg*2;
            const float b0 = bias[nA], b1 = bias[nA + 1];
#pragma unroll
            for (int half = 0; half < 2; half++) {
                const int m = mA + half * 8;
                float vx = acc[mt][nt][half*2 + 0] + b0;
                float vy = acc[mt][nt][half*2 + 1] + b1;
                if (dst == 0) {
                    float2 v; v.x = vx; v.y = vy;
                    *(float2*)&Yout[(size_t)m * Hh + nA] = v;
                } else {
                    const int bb   = m / Ss;
                    const int s    = m - bb * Ss;
                    const int head = nA >> 6;
                    const int d    = nA & 63;
                    uint32_t* dp = (dst == 1) ? g_qt : (dst == 2) ? g_kt : g_vt;
                    uint2 u;
                    u.x = f2tf32(vx * qscale);
                    u.y = f2tf32(vy * qscale);
                    *(uint2*)&dp[(((size_t)(bb * NHh + head)) * Ss + s) * HDd + d] = u;
                }
            }
        }
    }
}

__global__ __launch_bounds__(128)
void gemm_qkv(const float* __restrict__ bq, const float* __restrict__ bk,
              const float* __restrict__ bv)
{
    extern __shared__ uint32_t smem_g[];
    const int z = blockIdx.z;
    const float* bias = (z == 0) ? bq : (z == 1) ? bk : bv;
    gemm_tc_body(g_xt, g_wt + (size_t)z * Hh * Hh, bias, nullptr,
                 z + 1, blockIdx.x, blockIdx.y, smem_g);
}

__global__ __launch_bounds__(128)
void gemm_out(const float* __restrict__ bo, float* __restrict__ out)
{
    extern __shared__ uint32_t smem_g[];
    gemm_tc_body(g_ctxt, g_wt + (size_t)3 * Hh * Hh, bo, out,
                 0, blockIdx.x, blockIdx.y, smem_g);
}

// ---------------------------------------------------------------------------
// Tensor-core causal flash attention (tf32 mma), v6:
// 128 q-rows per CTA, 8 warps (16 rows each), K/V tiles of 64 keys shared
// CTA-wide (halves SMEM-fill traffic vs 64-row tiles).
// grid: (S/128, B*NH) = (16, 32), block 256. Heavy q-tiles first.
// Warps skip compute for k-tiles fully after their rows (barriers still hit).
// Ps is strictly per-warp-striped: own 16 rows only (write then read).
// Dynamic SMEM: Ks 64x68 + Vs 64x72 + Ps 128x68 = 70656 bytes.
// ---------------------------------------------------------------------------
#define ATTN_SMEM ((64*68 + 64*72 + 128*68)*4)

__global__ __launch_bounds__(256)
void attn_tc()
{
    extern __shared__ uint32_t asmem[];
    uint32_t (*Ks)[68] = (uint32_t(*)[68])asmem;                    // K tile
    uint32_t (*Vs)[72] = (uint32_t(*)[72])(asmem + 64*68);          // V tile
    uint32_t (*Ps)[68] = (uint32_t(*)[68])(asmem + 64*68 + 64*72);  // Q staging / P

    const int tid  = threadIdx.x;
    const int lane = tid & 31;
    const int wid  = tid >> 5;      // 0..7
    const int g    = lane >> 2;     // 0..7
    const int tg   = lane & 3;      // 0..3
    const int qb   = gridDim.x - 1 - blockIdx.x;   // heavy tiles first
    const int bh   = blockIdx.y;
    const int q0   = qb * 128;
    const int R0   = wid * 16;      // warp's q-row base within 128-row tile

    const uint32_t* Qg = g_qt + (size_t)bh * Ss * HDd;
    const uint32_t* Kg = g_kt + (size_t)bh * Ss * HDd;
    const uint32_t* Vg = g_vt + (size_t)bh * Ss * HDd;

    // ---- stage Q (tf32, pre-scaled) into Ps, pull fragments ----
    for (int u = tid; u < 128 * 16; u += 256) {
        const int r = u >> 4;
        const int c = (u & 15) << 2;
        *(uint4*)&Ps[r][c] = *(const uint4*)&Qg[(size_t)(q0 + r) * 64 + c];
    }
    __syncthreads();

    uint32_t qf[8][4];
#pragma unroll
    for (int kc = 0; kc < 8; kc++) {
        qf[kc][0] = Ps[R0 + g][kc * 8 + tg];
        qf[kc][1] = Ps[R0 + g + 8][kc * 8 + tg];
        qf[kc][2] = Ps[R0 + g][kc * 8 + tg + 4];
        qf[kc][3] = Ps[R0 + g + 8][kc * 8 + tg + 4];
    }
    // NOTE: each warp only ever touches Ps rows [R0, R0+16) from here on,
    // and extraction precedes any P store in warp program order -> no
    // cross-warp hazard on Ps; no extra barrier needed.

    float oacc[8][4];
#pragma unroll
    for (int nt = 0; nt < 8; nt++)
#pragma unroll
        for (int r = 0; r < 4; r++) oacc[nt][r] = 0.f;
    float m0 = -1e30f, m1 = -1e30f, l0 = 0.f, l1 = 0.f;

    const int kbmax = 2 * qb + 1;
    const int rowlast = q0 + R0 + 15;   // last q row this warp owns

    for (int kb = 0; kb <= kbmax; kb++) {
        const int k0 = kb * 64;
        __syncthreads();   // prev tile's Ks/Vs reads complete

        // ---- load K tile -> Ks, V tile -> Vs (pure uint4 copies) ----
        for (int u = tid; u < 64 * 16; u += 256) {
            const int r = u >> 4;
            const int c = (u & 15) << 2;
            *(uint4*)&Ks[r][c] = *(const uint4*)&Kg[(size_t)(k0 + r) * 64 + c];
            *(uint4*)&Vs[r][c] = *(const uint4*)&Vg[(size_t)(k0 + r) * 64 + c];
        }
        __syncthreads();

        if (k0 > rowlast) continue;   // tile entirely after this warp's rows

        // ---- S = Q K^T (Q pre-scaled) ----
        float sacc[8][4];
#pragma unroll
        for (int nt = 0; nt < 8; nt++)
#pragma unroll
            for (int r = 0; r < 4; r++) sacc[nt][r] = 0.f;

#pragma unroll
        for (int kc = 0; kc < 8; kc++) {
#pragma unroll
            for (int nt = 0; nt < 8; nt++) {
                uint32_t kf[2];
                kf[0] = Ks[nt * 8 + g][kc * 8 + tg];
                kf[1] = Ks[nt * 8 + g][kc * 8 + tg + 4];
                mma_tf32(sacc[nt], qf[kc], kf, sacc[nt]);
            }
        }

        // ---- causal mask (only if tile can overlap the diagonal) ----
        const int gr0 = q0 + R0 + g;       // global row of sacc[.][0,1]
        const int gr1 = gr0 + 8;           // global row of sacc[.][2,3]
        if (k0 + 63 > gr0) {
#pragma unroll
            for (int nt = 0; nt < 8; nt++) {
                const int gc = k0 + nt * 8 + tg * 2;
                if (gc > gr0)     sacc[nt][0] = -1e30f;
                if (gc + 1 > gr0) sacc[nt][1] = -1e30f;
                if (gc > gr1)     sacc[nt][2] = -1e30f;
                if (gc + 1 > gr1) sacc[nt][3] = -1e30f;
            }
        }

        // ---- online softmax: row max ----
        float bm0 = -1e30f, bm1 = -1e30f;
#pragma unroll
        for (int nt = 0; nt < 8; nt++) {
            bm0 = fmaxf(bm0, fmaxf(sacc[nt][0], sacc[nt][1]));
            bm1 = fmaxf(bm1, fmaxf(sacc[nt][2], sacc[nt][3]));
        }
        bm0 = fmaxf(bm0, __shfl_xor_sync(0xffffffffu, bm0, 1));
        bm0 = fmaxf(bm0, __shfl_xor_sync(0xffffffffu, bm0, 2));
        bm1 = fmaxf(bm1, __shfl_xor_sync(0xffffffffu, bm1, 1));
        bm1 = fmaxf(bm1, __shfl_xor_sync(0xffffffffu, bm1, 2));

        const float nm0 = fmaxf(m0, bm0);
        const float nm1 = fmaxf(m1, bm1);
        const float c0f = __expf(m0 - nm0);
        const float c1f = __expf(m1 - nm1);
        m0 = nm0; m1 = nm1;
#pragma unroll
        for (int nt = 0; nt < 8; nt++) {
            oacc[nt][0] *= c0f; oacc[nt][1] *= c0f;
            oacc[nt][2] *= c1f; oacc[nt][3] *= c1f;
        }
        l0 *= c0f; l1 *= c1f;

        // ---- P = exp(S - m) -> Ps (own warp stripe only) ----
        float rs0 = 0.f, rs1 = 0.f;
#pragma unroll
        for (int nt = 0; nt < 8; nt++) {
            const int cc = nt * 8 + tg * 2;
            float p0 = __expf(sacc[nt][0] - nm0);
            float p1 = __expf(sacc[nt][1] - nm0);
            float p2 = __expf(sacc[nt][2] - nm1);
            float p3 = __expf(sacc[nt][3] - nm1);
            rs0 += p0 + p1;
            rs1 += p2 + p3;
            Ps[R0 + g][cc]         = f2tf32(p0);
            Ps[R0 + g][cc + 1]     = f2tf32(p1);
            Ps[R0 + g + 8][cc]     = f2tf32(p2);
            Ps[R0 + g + 8][cc + 1] = f2tf32(p3);
        }
        rs0 += __shfl_xor_sync(0xffffffffu, rs0, 1);
        rs0 += __shfl_xor_sync(0xffffffffu, rs0, 2);
        rs1 += __shfl_xor_sync(0xffffffffu, rs1, 1);
        rs1 += __shfl_xor_sync(0xffffffffu, rs1, 2);
        l0 += rs0; l1 += rs1;

        __syncwarp();      // P stripe visible within warp

        // ---- O += P @ V ----
#pragma unroll
        for (int kc = 0; kc < 8; kc++) {
            uint32_t af[4];
            af[0] = Ps[R0 + g][kc * 8 + tg];
            af[1] = Ps[R0 + g + 8][kc * 8 + tg];
            af[2] = Ps[R0 + g][kc * 8 + tg + 4];
            af[3] = Ps[R0 + g + 8][kc * 8 + tg + 4];
#pragma unroll
            for (int nt = 0; nt < 8; nt++) {
                uint32_t bf[2];
                bf[0] = Vs[kc * 8 + tg][nt * 8 + g];
                bf[1] = Vs[kc * 8 + tg + 4][nt * 8 + g];
                mma_tf32(oacc[nt], af, bf, oacc[nt]);
            }
        }
    }

    // ---- normalize + writeback ctx (tf32) ----
    const float inv0 = 1.f / l0;
    const float inv1 = 1.f / l1;
    const int b    = bh / NHh;
    const int head = bh - b * NHh;
    const int s0   = q0 + R0 + g;
    const int s1   = s0 + 8;
#pragma unroll
    for (int nt = 0; nt < 8; nt++) {
        const int col = head * 64 + nt * 8 + tg * 2;
        uint2 v0, v1;
        v0.x = f2tf32(oacc[nt][0] * inv0); v0.y = f2tf32(oacc[nt][1] * inv0);
        v1.x = f2tf32(oacc[nt][2] * inv1); v1.y = f2tf32(oacc[nt][3] * inv1);
        *(uint2*)&g_ctxt[((size_t)(b * Ss) + s0) * Hh + col] = v0;
        *(uint2*)&g_ctxt[((size_t)(b * Ss) + s1) * Hh + col] = v1;
    }
}

// ---------------------------------------------------------------------------
// kernel_launch
// inputs: 0 hidden_states, 1 Wq, 2 bq, 3 Wk, 4 bk, 5 Wv, 6 bv, 7 Wo, 8 bo
// ---------------------------------------------------------------------------
extern "C" void kernel_launch(void* const* d_in, const int* in_sizes, int n_in,
                              void* d_out, int out_size)
{
    const float* x  = (const float*)d_in[0];
    const float* Wq = (const float*)d_in[1];
    const float* bq = (const float*)d_in[2];
    const float* Wk = (const float*)d_in[3];
    const float* bk = (const float*)d_in[4];
    const float* Wv = (const float*)d_in[5];
    const float* bv = (const float*)d_in[6];
    const float* Wo = (const float*)d_in[7];
    const float* bo = (const float*)d_in[8];
    float* out = (float*)d_out;

    cudaFuncSetAttribute(gemm_qkv, cudaFuncAttributeMaxDynamicSharedMemorySize, GEMM_SMEM);
    cudaFuncSetAttribute(gemm_out, cudaFuncAttributeMaxDynamicSharedMemorySize, GEMM_SMEM);
    cudaFuncSetAttribute(attn_tc,  cudaFuncAttributeMaxDynamicSharedMemorySize, ATTN_SMEM);

    preconv<<<4096, 256>>>(x, Wq, Wk, Wv, Wo);

    dim3 qkvgrid(Hh / 128, Mrows / 128, 3);   // (8, 32, 3)
    gemm_qkv<<<qkvgrid, 128, GEMM_SMEM>>>(bq, bk, bv);

    dim3 agrid(Ss / 128, Bb * NHh);           // (16, 32)
    attn_tc<<<agrid, 256, ATTN_SMEM>>>();

    dim3 ogrid(Hh / 128, Mrows / 128);        // (8, 32)
    gemm_out<<<ogrid, 128, GEMM_SMEM>>>(bo, out);
}

// round 9
// speedup vs baseline: 2.2002x; 2.2002x over previous
#include <cuda_runtime.h>
#include <cuda_fp16.h>
#include <cstdint>

// Problem constants
#define Bb   2
#define Ss   2048
#define Hh   1024
#define NHh  16
#define HDd  64
#define Mrows (Bb*Ss)   // 4096

// ---------------------------------------------------------------------------
// Device scratch (no allocations allowed).
// fp16 payloads packed as half2 in uint32; tf32 payloads as uint32 bits.
// ---------------------------------------------------------------------------
__device__ uint32_t g_xh[Mrows*Hh/2];      // X fp16 (half2-packed)
__device__ uint32_t g_wh[4*Hh*Hh/2];       // Wq,Wk,Wv,Wo fp16
__device__ uint32_t g_qt[Bb*NHh*Ss*HDd];   // Q (pre-scaled by 1/8), tf32, [b,h,s,d]
__device__ uint32_t g_kt[Bb*NHh*Ss*HDd];   // K tf32
__device__ uint32_t g_vt[Bb*NHh*Ss*HDd];   // V tf32
__device__ uint32_t g_ctxh[Bb*Ss*Hh/2];    // attention output fp16, [b,s,h]

__device__ __forceinline__ uint32_t f2tf32(float x) {
    uint32_t r;
    asm("cvt.rna.tf32.f32 %0, %1;" : "=r"(r) : "f"(x));
    return r;
}
__device__ __forceinline__ uint32_t packh2(float a, float b) {
    __half2 h = __floats2half2_rn(a, b);
    return *(uint32_t*)&h;
}

__device__ __forceinline__ void mma_tf32(float d[4], const uint32_t a[4],
                                         const uint32_t b[2], const float c[4]) {
    asm volatile(
        "mma.sync.aligned.m16n8k8.row.col.f32.tf32.tf32.f32 "
        "{%0,%1,%2,%3}, {%4,%5,%6,%7}, {%8,%9}, {%10,%11,%12,%13};\n"
        : "=f"(d[0]), "=f"(d[1]), "=f"(d[2]), "=f"(d[3])
        : "r"(a[0]), "r"(a[1]), "r"(a[2]), "r"(a[3]),
          "r"(b[0]), "r"(b[1]),
          "f"(c[0]), "f"(c[1]), "f"(c[2]), "f"(c[3]));
}

__device__ __forceinline__ void mma_f16(float d[4], const uint32_t a[4],
                                        const uint32_t b[2], const float c[4]) {
    asm volatile(
        "mma.sync.aligned.m16n8k16.row.col.f32.f16.f16.f32 "
        "{%0,%1,%2,%3}, {%4,%5,%6,%7}, {%8,%9}, {%10,%11,%12,%13};\n"
        : "=f"(d[0]), "=f"(d[1]), "=f"(d[2]), "=f"(d[3])
        : "r"(a[0]), "r"(a[1]), "r"(a[2]), "r"(a[3]),
          "r"(b[0]), "r"(b[1]),
          "f"(c[0]), "f"(c[1]), "f"(c[2]), "f"(c[3]));
}

__device__ __forceinline__ void cp_async16(uint32_t smem_addr, const void* gptr) {
    asm volatile("cp.async.cg.shared.global [%0], [%1], 16;\n"
                 :: "r"(smem_addr), "l"(gptr));
}
__device__ __forceinline__ uint32_t s2u(const void* p) {
    return (uint32_t)__cvta_generic_to_shared(p);
}

// ---------------------------------------------------------------------------
// Prologue: convert X and the 4 weight matrices to fp16 once.
// ---------------------------------------------------------------------------
__global__ __launch_bounds__(256)
void preconv(const float* __restrict__ x,
             const float* __restrict__ wq, const float* __restrict__ wk,
             const float* __restrict__ wv, const float* __restrict__ wo)
{
    const int i = blockIdx.x * blockDim.x + threadIdx.x;
    const int NX4 = (Mrows * Hh) / 4;   // 1,048,576 float4 chunks
    const int NW4 = (Hh * Hh) / 4;      // 262,144

    if (i < NX4) {
        float4 v = ((const float4*)x)[i];
        uint2 u;
        u.x = packh2(v.x, v.y);
        u.y = packh2(v.z, v.w);
        ((uint2*)g_xh)[i] = u;
    }
    if (i < NW4) {
        const float* ws[4] = {wq, wk, wv, wo};
#pragma unroll
        for (int z = 0; z < 4; z++) {
            float4 v = ((const float4*)ws[z])[i];
            uint2 u;
            u.x = packh2(v.x, v.y);
            u.y = packh2(v.z, v.w);
            ((uint2*)(g_wh + (size_t)z * (Hh * Hh / 2)))[i] = u;
        }
    }
}

// ---------------------------------------------------------------------------
// fp16 GEMM (m16n8k16) with cp.async 2-stage pipeline.
// Round-6 proven structure: 128 threads, 4 warps (2m x 2n), warp tile 64x64,
// CTA tile 128x128, BK=32 halves (16 u32 cols per row, padded to 20).
// A,B in u32-packed half2, row stride 512 u32 (1024 halves).
// dst: 0 -> Yout fp32; 1/2/3 -> g_qt/kt/vt (tf32).
// Dynamic SMEM: 2 stages x (A 128x20 + B 128x20) u32 = 40960 bytes.
// ---------------------------------------------------------------------------
#define GEMM_STG   (2*128*20)                 // u32 words per stage (A+B)
#define GEMM_SMEM  (2*GEMM_STG*4)             // bytes = 40960
#define LDAU       (Hh/2)                     // 512 u32 per row

__device__ __forceinline__
void gemm_load_stage(const uint32_t* __restrict__ A, const uint32_t* __restrict__ Bm,
                     uint32_t* dstA, int m0, int n0, int k0u, int tid)
{
    uint32_t* dstB = dstA + 128*20;
#pragma unroll
    for (int j = 0; j < 4; j++) {
        const int id  = j * 128 + tid;     // 0..511
        const int row = id >> 2;
        const int col = (id & 3) * 4;
        cp_async16(s2u(dstA + row*20 + col), A  + (size_t)(m0+row)*LDAU + k0u + col);
        cp_async16(s2u(dstB + row*20 + col), Bm + (size_t)(n0+row)*LDAU + k0u + col);
    }
}

__device__ __forceinline__
void gemm_tc_body(const uint32_t* __restrict__ A, const uint32_t* __restrict__ Bm,
                  const float* __restrict__ bias, float* __restrict__ Yout,
                  int dst, int bx, int by, uint32_t* smem)
{
    const int tid  = threadIdx.x;
    const int lane = tid & 31;
    const int wid  = tid >> 5;
    const int wm   = (wid & 1) * 64;
    const int wn   = (wid >> 1) * 64;
    const int m0   = by * 128;
    const int n0   = bx * 128;
    const int g    = lane >> 2;
    const int tg   = lane & 3;

    float acc[4][8][4];
#pragma unroll
    for (int mt = 0; mt < 4; mt++)
#pragma unroll
        for (int nt = 0; nt < 8; nt++)
#pragma unroll
            for (int r = 0; r < 4; r++) acc[mt][nt][r] = 0.f;

    gemm_load_stage(A, Bm, smem, m0, n0, 0, tid);
    asm volatile("cp.async.commit_group;\n");

    for (int kt = 0; kt < 32; kt++) {
        if (kt + 1 < 32) {
            gemm_load_stage(A, Bm, smem + ((kt+1)&1)*GEMM_STG, m0, n0, (kt+1)*16, tid);
            asm volatile("cp.async.commit_group;\n");
            asm volatile("cp.async.wait_group 1;\n");
        } else {
            asm volatile("cp.async.wait_group 0;\n");
        }
        __syncthreads();

        const uint32_t* As = smem + (kt & 1) * GEMM_STG;
        const uint32_t* Bs = As + 128*20;

        // BK=32 halves = 2 chunks of k16; u32 col offsets 0 and 8
#pragma unroll
        for (int kc8 = 0; kc8 < 16; kc8 += 8) {
            uint32_t af[4][4];
            uint32_t bf[8][2];
#pragma unroll
            for (int mt = 0; mt < 4; mt++) {
                const uint32_t* r0p = As + (wm + mt*16 + g)*20 + kc8;
                af[mt][0] = r0p[tg];            // row g,   k 0..7   (2 halves)
                af[mt][2] = r0p[tg + 4];        // row g,   k 8..15
                const uint32_t* r1p = r0p + 8*20;
                af[mt][1] = r1p[tg];            // row g+8, k 0..7
                af[mt][3] = r1p[tg + 4];        // row g+8, k 8..15
            }
#pragma unroll
            for (int nt = 0; nt < 8; nt++) {
                const uint32_t* cp_ = Bs + (wn + nt*8 + g)*20 + kc8;
                bf[nt][0] = cp_[tg];
                bf[nt][1] = cp_[tg + 4];
            }
#pragma unroll
            for (int mt = 0; mt < 4; mt++)
#pragma unroll
                for (int nt = 0; nt < 8; nt++)
                    mma_f16(acc[mt][nt], af[mt], bf[nt], acc[mt][nt]);
        }
        __syncthreads();
    }

    // epilogue (fragment layout identical to tf32 version)
    const float qscale = (dst == 1) ? 0.125f : 1.0f;
#pragma unroll
    for (int mt = 0; mt < 4; mt++) {
#pragma unroll
        for (int nt = 0; nt < 8; nt++) {
            const int mA = m0 + wm + mt*16 + g;
            const int nA = n0 + wn + nt*8 + tg*2;
            const float b0 = bias[nA], b1 = bias[nA + 1];
#pragma unroll
            for (int half = 0; half < 2; half++) {
                const int m = mA + half * 8;
                float vx = acc[mt][nt][half*2 + 0] + b0;
                float vy = acc[mt][nt][half*2 + 1] + b1;
                if (dst == 0) {
                    float2 v; v.x = vx; v.y = vy;
                    *(float2*)&Yout[(size_t)m * Hh + nA] = v;
                } else {
                    const int bb   = m / Ss;
                    const int s    = m - bb * Ss;
                    const int head = nA >> 6;
                    const int d    = nA & 63;
                    uint32_t* dp = (dst == 1) ? g_qt : (dst == 2) ? g_kt : g_vt;
                    uint2 u;
                    u.x = f2tf32(vx * qscale);
                    u.y = f2tf32(vy * qscale);
                    *(uint2*)&dp[(((size_t)(bb * NHh + head)) * Ss + s) * HDd + d] = u;
                }
            }
        }
    }
}

__global__ __launch_bounds__(128)
void gemm_qkv(const float* __restrict__ bq, const float* __restrict__ bk,
              const float* __restrict__ bv)
{
    extern __shared__ uint32_t smem_g[];
    const int z = blockIdx.z;
    const float* bias = (z == 0) ? bq : (z == 1) ? bk : bv;
    gemm_tc_body(g_xh, g_wh + (size_t)z * (Hh * Hh / 2), bias, nullptr,
                 z + 1, blockIdx.x, blockIdx.y, smem_g);
}

__global__ __launch_bounds__(128)
void gemm_out(const float* __restrict__ bo, float* __restrict__ out)
{
    extern __shared__ uint32_t smem_g[];
    gemm_tc_body(g_ctxh, g_wh + (size_t)3 * (Hh * Hh / 2), bo, out,
                 0, blockIdx.x, blockIdx.y, smem_g);
}

// ---------------------------------------------------------------------------
// Tensor-core causal flash attention (tf32 mma) — round-6 measured winner,
// verbatim except the writeback packs ctx as fp16 for the fp16 out-GEMM.
// grid: (S/64, B*NH), block 128 (4 warps). Heavy q-tiles first.
// Dynamic SMEM: Ks 64x68 + Vs 64x72 + Ps 64x68 = 53248 bytes.
// ---------------------------------------------------------------------------
#define ATTN_SMEM ((64*68 + 64*72 + 64*68)*4)

__global__ __launch_bounds__(128)
void attn_tc()
{
    extern __shared__ uint32_t asmem[];
    uint32_t (*Ks)[68] = (uint32_t(*)[68])asmem;                    // Q staging / K tile
    uint32_t (*Vs)[72] = (uint32_t(*)[72])(asmem + 64*68);          // V tile
    uint32_t (*Ps)[68] = (uint32_t(*)[68])(asmem + 64*68 + 64*72);  // P tile

    const int tid  = threadIdx.x;
    const int lane = tid & 31;
    const int wid  = tid >> 5;      // 0..3
    const int g    = lane >> 2;     // 0..7
    const int tg   = lane & 3;      // 0..3
    const int qb   = gridDim.x - 1 - blockIdx.x;   // heavy tiles first
    const int bh   = blockIdx.y;
    const int q0   = qb * 64;
    const int R0   = wid * 16;      // warp's q-row base within tile

    const uint32_t* Qg = g_qt + (size_t)bh * Ss * HDd;
    const uint32_t* Kg = g_kt + (size_t)bh * Ss * HDd;
    const uint32_t* Vg = g_vt + (size_t)bh * Ss * HDd;

    // ---- stage Q into Ks (already tf32 + pre-scaled), pull fragments ----
    for (int u = tid; u < 64 * 16; u += 128) {
        const int r = u >> 4;
        const int c = (u & 15) << 2;
        *(uint4*)&Ks[r][c] = *(const uint4*)&Qg[(size_t)(q0 + r) * 64 + c];
    }
    __syncthreads();

    uint32_t qf[8][4];
#pragma unroll
    for (int kc = 0; kc < 8; kc++) {
        qf[kc][0] = Ks[R0 + g][kc * 8 + tg];
        qf[kc][1] = Ks[R0 + g + 8][kc * 8 + tg];
        qf[kc][2] = Ks[R0 + g][kc * 8 + tg + 4];
        qf[kc][3] = Ks[R0 + g + 8][kc * 8 + tg + 4];
    }

    float oacc[8][4];
#pragma unroll
    for (int nt = 0; nt < 8; nt++)
#pragma unroll
        for (int r = 0; r < 4; r++) oacc[nt][r] = 0.f;
    float m0 = -1e30f, m1 = -1e30f, l0 = 0.f, l1 = 0.f;

    for (int kb = 0; kb <= qb; kb++) {
        const int k0 = kb * 64;
        __syncthreads();   // prev tile's Ks/Vs/Ps reads complete (and Q frags, kb=0)

        // ---- load K tile -> Ks, V tile -> Vs (pure uint4 copies) ----
        for (int u = tid; u < 64 * 16; u += 128) {
            const int r = u >> 4;
            const int c = (u & 15) << 2;
            *(uint4*)&Ks[r][c] = *(const uint4*)&Kg[(size_t)(k0 + r) * 64 + c];
            *(uint4*)&Vs[r][c] = *(const uint4*)&Vg[(size_t)(k0 + r) * 64 + c];
        }
        __syncthreads();

        // ---- S = Q K^T (Q pre-scaled) ----
        float sacc[8][4];
#pragma unroll
        for (int nt = 0; nt < 8; nt++)
#pragma unroll
            for (int r = 0; r < 4; r++) sacc[nt][r] = 0.f;

#pragma unroll
        for (int kc = 0; kc < 8; kc++) {
#pragma unroll
            for (int nt = 0; nt < 8; nt++) {
                uint32_t kf[2];
                kf[0] = Ks[nt * 8 + g][kc * 8 + tg];
                kf[1] = Ks[nt * 8 + g][kc * 8 + tg + 4];
                mma_tf32(sacc[nt], qf[kc], kf, sacc[nt]);
            }
        }

        // ---- causal mask on diagonal tile ----
        if (kb == qb) {
            const int r0 = R0 + g;
            const int r1 = r0 + 8;
#pragma unroll
            for (int nt = 0; nt < 8; nt++) {
                const int c0 = nt * 8 + tg * 2;
                if (c0 > r0)     sacc[nt][0] = -1e30f;
                if (c0 + 1 > r0) sacc[nt][1] = -1e30f;
                if (c0 > r1)     sacc[nt][2] = -1e30f;
                if (c0 + 1 > r1) sacc[nt][3] = -1e30f;
            }
        }

        // ---- online softmax: row max ----
        float bm0 = -1e30f, bm1 = -1e30f;
#pragma unroll
        for (int nt = 0; nt < 8; nt++) {
            bm0 = fmaxf(bm0, fmaxf(sacc[nt][0], sacc[nt][1]));
            bm1 = fmaxf(bm1, fmaxf(sacc[nt][2], sacc[nt][3]));
        }
        bm0 = fmaxf(bm0, __shfl_xor_sync(0xffffffffu, bm0, 1));
        bm0 = fmaxf(bm0, __shfl_xor_sync(0xffffffffu, bm0, 2));
        bm1 = fmaxf(bm1, __shfl_xor_sync(0xffffffffu, bm1, 1));
        bm1 = fmaxf(bm1, __shfl_xor_sync(0xffffffffu, bm1, 2));

        const float nm0 = fmaxf(m0, bm0);
        const float nm1 = fmaxf(m1, bm1);
        const float c0f = __expf(m0 - nm0);
        const float c1f = __expf(m1 - nm1);
        m0 = nm0; m1 = nm1;
#pragma unroll
        for (int nt = 0; nt < 8; nt++) {
            oacc[nt][0] *= c0f; oacc[nt][1] *= c0f;
            oacc[nt][2] *= c1f; oacc[nt][3] *= c1f;
        }
        l0 *= c0f; l1 *= c1f;

        // ---- P = exp(S - m) -> Ps (own warp stripe; no cross-warp use) ----
        float rs0 = 0.f, rs1 = 0.f;
#pragma unroll
        for (int nt = 0; nt < 8; nt++) {
            const int cc = nt * 8 + tg * 2;
            float p0 = __expf(sacc[nt][0] - nm0);
            float p1 = __expf(sacc[nt][1] - nm0);
            float p2 = __expf(sacc[nt][2] - nm1);
            float p3 = __expf(sacc[nt][3] - nm1);
            rs0 += p0 + p1;
            rs1 += p2 + p3;
            Ps[R0 + g][cc]         = f2tf32(p0);
            Ps[R0 + g][cc + 1]     = f2tf32(p1);
            Ps[R0 + g + 8][cc]     = f2tf32(p2);
            Ps[R0 + g + 8][cc + 1] = f2tf32(p3);
        }
        rs0 += __shfl_xor_sync(0xffffffffu, rs0, 1);
        rs0 += __shfl_xor_sync(0xffffffffu, rs0, 2);
        rs1 += __shfl_xor_sync(0xffffffffu, rs1, 1);
        rs1 += __shfl_xor_sync(0xffffffffu, rs1, 2);
        l0 += rs0; l1 += rs1;

        __syncwarp();      // P stripe visible within warp

        // ---- O += P @ V ----
#pragma unroll
        for (int kc = 0; kc < 8; kc++) {
            uint32_t af[4];
            af[0] = Ps[R0 + g][kc * 8 + tg];
            af[1] = Ps[R0 + g + 8][kc * 8 + tg];
            af[2] = Ps[R0 + g][kc * 8 + tg + 4];
            af[3] = Ps[R0 + g + 8][kc * 8 + tg + 4];
#pragma unroll
            for (int nt = 0; nt < 8; nt++) {
                uint32_t bf[2];
                bf[0] = Vs[kc * 8 + tg][nt * 8 + g];
                bf[1] = Vs[kc * 8 + tg + 4][nt * 8 + g];
                mma_tf32(oacc[nt], af, bf, oacc[nt]);
            }
        }
    }

    // ---- normalize + writeback ctx as fp16 (half2 over adjacent dims) ----
    const float inv0 = 1.f / l0;
    const float inv1 = 1.f / l1;
    const int b    = bh / NHh;
    const int head = bh - b * NHh;
    const int s0   = q0 + R0 + g;
    const int s1   = s0 + 8;
#pragma unroll
    for (int nt = 0; nt < 8; nt++) {
        const int col = head * 64 + nt * 8 + tg * 2;   // even
        g_ctxh[((size_t)(b * Ss) + s0) * (Hh/2) + (col >> 1)] =
            packh2(oacc[nt][0] * inv0, oacc[nt][1] * inv0);
        g_ctxh[((size_t)(b * Ss) + s1) * (Hh/2) + (col >> 1)] =
            packh2(oacc[nt][2] * inv1, oacc[nt][3] * inv1);
    }
}

// ---------------------------------------------------------------------------
// kernel_launch
// inputs: 0 hidden_states, 1 Wq, 2 bq, 3 Wk, 4 bk, 5 Wv, 6 bv, 7 Wo, 8 bo
// ---------------------------------------------------------------------------
extern "C" void kernel_launch(void* const* d_in, const int* in_sizes, int n_in,
                              void* d_out, int out_size)
{
    const float* x  = (const float*)d_in[0];
    const float* Wq = (const float*)d_in[1];
    const float* bq = (const float*)d_in[2];
    const float* Wk = (const float*)d_in[3];
    const float* bk = (const float*)d_in[4];
    const float* Wv = (const float*)d_in[5];
    const float* bv = (const float*)d_in[6];
    const float* Wo = (const float*)d_in[7];
    const float* bo = (const float*)d_in[8];
    float* out = (float*)d_out;

    cudaFuncSetAttribute(gemm_qkv, cudaFuncAttributeMaxDynamicSharedMemorySize, GEMM_SMEM);
    cudaFuncSetAttribute(gemm_out, cudaFuncAttributeMaxDynamicSharedMemorySize, GEMM_SMEM);
    cudaFuncSetAttribute(attn_tc,  cudaFuncAttributeMaxDynamicSharedMemorySize, ATTN_SMEM);

    preconv<<<4096, 256>>>(x, Wq, Wk, Wv, Wo);

    dim3 qkvgrid(Hh / 128, Mrows / 128, 3);   // (8, 32, 3)
    gemm_qkv<<<qkvgrid, 128, GEMM_SMEM>>>(bq, bk, bv);

    dim3 agrid(Ss / 64, Bb * NHh);            // (32, 32)
    attn_tc<<<agrid, 128, ATTN_SMEM>>>();

    dim3 ogrid(Hh / 128, Mrows / 128);        // (8, 32)
    gemm_out<<<ogrid, 128, GEMM_SMEM>>>(bo, out);
}

// round 10
// speedup vs baseline: 2.5234x; 1.1469x over previous
#include <cuda_runtime.h>
#include <cuda_fp16.h>
#include <cstdint>

// Problem constants
#define Bb   2
#define Ss   2048
#define Hh   1024
#define NHh  16
#define HDd  64
#define Mrows (Bb*Ss)   // 4096

// ---------------------------------------------------------------------------
// Device scratch (no allocations allowed). fp16 packed as half2 in uint32.
// ---------------------------------------------------------------------------
__device__ uint32_t g_xh[Mrows*Hh/2];        // X fp16
__device__ uint32_t g_wh[4*Hh*Hh/2];         // Wq,Wk,Wv,Wo fp16
__device__ uint32_t g_qh[Bb*NHh*Ss*HDd/2];   // Q fp16 (pre-scaled 1/8), [b,h,s,d/2]
__device__ uint32_t g_kh[Bb*NHh*Ss*HDd/2];   // K fp16
__device__ uint32_t g_vh[Bb*NHh*Ss*HDd/2];   // V fp16
__device__ uint32_t g_ctxh[Bb*Ss*Hh/2];      // attention output fp16, [b,s,h]

__device__ __forceinline__ uint32_t packh2(float a, float b) {
    __half2 h = __floats2half2_rn(a, b);
    return *(uint32_t*)&h;
}

__device__ __forceinline__ void mma_f16(float d[4], const uint32_t a[4],
                                        const uint32_t b[2], const float c[4]) {
    asm volatile(
        "mma.sync.aligned.m16n8k16.row.col.f32.f16.f16.f32 "
        "{%0,%1,%2,%3}, {%4,%5,%6,%7}, {%8,%9}, {%10,%11,%12,%13};\n"
        : "=f"(d[0]), "=f"(d[1]), "=f"(d[2]), "=f"(d[3])
        : "r"(a[0]), "r"(a[1]), "r"(a[2]), "r"(a[3]),
          "r"(b[0]), "r"(b[1]),
          "f"(c[0]), "f"(c[1]), "f"(c[2]), "f"(c[3]));
}

__device__ __forceinline__ void cp_async16(uint32_t smem_addr, const void* gptr) {
    asm volatile("cp.async.cg.shared.global [%0], [%1], 16;\n"
                 :: "r"(smem_addr), "l"(gptr));
}
__device__ __forceinline__ uint32_t s2u(const void* p) {
    return (uint32_t)__cvta_generic_to_shared(p);
}

// ---------------------------------------------------------------------------
// Prologue: convert X and the 4 weight matrices to fp16 once.
// ---------------------------------------------------------------------------
__global__ __launch_bounds__(256)
void preconv(const float* __restrict__ x,
             const float* __restrict__ wq, const float* __restrict__ wk,
             const float* __restrict__ wv, const float* __restrict__ wo)
{
    const int i = blockIdx.x * blockDim.x + threadIdx.x;
    const int NX4 = (Mrows * Hh) / 4;
    const int NW4 = (Hh * Hh) / 4;

    if (i < NX4) {
        float4 v = ((const float4*)x)[i];
        uint2 u;
        u.x = packh2(v.x, v.y);
        u.y = packh2(v.z, v.w);
        ((uint2*)g_xh)[i] = u;
    }
    if (i < NW4) {
        const float* ws[4] = {wq, wk, wv, wo};
#pragma unroll
        for (int z = 0; z < 4; z++) {
            float4 v = ((const float4*)ws[z])[i];
            uint2 u;
            u.x = packh2(v.x, v.y);
            u.y = packh2(v.z, v.w);
            ((uint2*)(g_wh + (size_t)z * (Hh * Hh / 2)))[i] = u;
        }
    }
}

// ---------------------------------------------------------------------------
// fp16 GEMM (m16n8k16) with cp.async 2-stage pipeline (round-9, proven).
// 128 threads, 4 warps (2m x 2n), warp tile 64x64, CTA 128x128, BK=32 halves.
// dst: 0 -> Yout fp32; 1/2/3 -> g_qh/kh/vh (fp16 packed).
// Dynamic SMEM: 2 stages x (A 128x20 + B 128x20) u32 = 40960 bytes.
// ---------------------------------------------------------------------------
#define GEMM_STG   (2*128*20)
#define GEMM_SMEM  (2*GEMM_STG*4)
#define LDAU       (Hh/2)

__device__ __forceinline__
void gemm_load_stage(const uint32_t* __restrict__ A, const uint32_t* __restrict__ Bm,
                     uint32_t* dstA, int m0, int n0, int k0u, int tid)
{
    uint32_t* dstB = dstA + 128*20;
#pragma unroll
    for (int j = 0; j < 4; j++) {
        const int id  = j * 128 + tid;
        const int row = id >> 2;
        const int col = (id & 3) * 4;
        cp_async16(s2u(dstA + row*20 + col), A  + (size_t)(m0+row)*LDAU + k0u + col);
        cp_async16(s2u(dstB + row*20 + col), Bm + (size_t)(n0+row)*LDAU + k0u + col);
    }
}

__device__ __forceinline__
void gemm_tc_body(const uint32_t* __restrict__ A, const uint32_t* __restrict__ Bm,
                  const float* __restrict__ bias, float* __restrict__ Yout,
                  int dst, int bx, int by, uint32_t* smem)
{
    const int tid  = threadIdx.x;
    const int lane = tid & 31;
    const int wid  = tid >> 5;
    const int wm   = (wid & 1) * 64;
    const int wn   = (wid >> 1) * 64;
    const int m0   = by * 128;
    const int n0   = bx * 128;
    const int g    = lane >> 2;
    const int tg   = lane & 3;

    float acc[4][8][4];
#pragma unroll
    for (int mt = 0; mt < 4; mt++)
#pragma unroll
        for (int nt = 0; nt < 8; nt++)
#pragma unroll
            for (int r = 0; r < 4; r++) acc[mt][nt][r] = 0.f;

    gemm_load_stage(A, Bm, smem, m0, n0, 0, tid);
    asm volatile("cp.async.commit_group;\n");

    for (int kt = 0; kt < 32; kt++) {
        if (kt + 1 < 32) {
            gemm_load_stage(A, Bm, smem + ((kt+1)&1)*GEMM_STG, m0, n0, (kt+1)*16, tid);
            asm volatile("cp.async.commit_group;\n");
            asm volatile("cp.async.wait_group 1;\n");
        } else {
            asm volatile("cp.async.wait_group 0;\n");
        }
        __syncthreads();

        const uint32_t* As = smem + (kt & 1) * GEMM_STG;
        const uint32_t* Bs = As + 128*20;

#pragma unroll
        for (int kc8 = 0; kc8 < 16; kc8 += 8) {
            uint32_t af[4][4];
            uint32_t bf[8][2];
#pragma unroll
            for (int mt = 0; mt < 4; mt++) {
                const uint32_t* r0p = As + (wm + mt*16 + g)*20 + kc8;
                af[mt][0] = r0p[tg];
                af[mt][2] = r0p[tg + 4];
                const uint32_t* r1p = r0p + 8*20;
                af[mt][1] = r1p[tg];
                af[mt][3] = r1p[tg + 4];
            }
#pragma unroll
            for (int nt = 0; nt < 8; nt++) {
                const uint32_t* cp_ = Bs + (wn + nt*8 + g)*20 + kc8;
                bf[nt][0] = cp_[tg];
                bf[nt][1] = cp_[tg + 4];
            }
#pragma unroll
            for (int mt = 0; mt < 4; mt++)
#pragma unroll
                for (int nt = 0; nt < 8; nt++)
                    mma_f16(acc[mt][nt], af[mt], bf[nt], acc[mt][nt]);
        }
        __syncthreads();
    }

    const float qscale = (dst == 1) ? 0.125f : 1.0f;
#pragma unroll
    for (int mt = 0; mt < 4; mt++) {
#pragma unroll
        for (int nt = 0; nt < 8; nt++) {
            const int mA = m0 + wm + mt*16 + g;
            const int nA = n0 + wn + nt*8 + tg*2;
            const float b0 = bias[nA], b1 = bias[nA + 1];
#pragma unroll
            for (int half = 0; half < 2; half++) {
                const int m = mA + half * 8;
                float vx = acc[mt][nt][half*2 + 0] + b0;
                float vy = acc[mt][nt][half*2 + 1] + b1;
                if (dst == 0) {
                    float2 v; v.x = vx; v.y = vy;
                    *(float2*)&Yout[(size_t)m * Hh + nA] = v;
                } else {
                    const int bb   = m / Ss;
                    const int s    = m - bb * Ss;
                    const int head = nA >> 6;
                    const int d    = nA & 63;
                    uint32_t* dp = (dst == 1) ? g_qh : (dst == 2) ? g_kh : g_vh;
                    dp[(((size_t)(bb * NHh + head)) * Ss + s) * (HDd/2) + (d >> 1)] =
                        packh2(vx * qscale, vy * qscale);
                }
            }
        }
    }
}

__global__ __launch_bounds__(128)
void gemm_qkv(const float* __restrict__ bq, const float* __restrict__ bk,
              const float* __restrict__ bv)
{
    extern __shared__ uint32_t smem_g[];
    const int z = blockIdx.z;
    const float* bias = (z == 0) ? bq : (z == 1) ? bk : bv;
    gemm_tc_body(g_xh, g_wh + (size_t)z * (Hh * Hh / 2), bias, nullptr,
                 z + 1, blockIdx.x, blockIdx.y, smem_g);
}

__global__ __launch_bounds__(128)
void gemm_out(const float* __restrict__ bo, float* __restrict__ out)
{
    extern __shared__ uint32_t smem_g[];
    gemm_tc_body(g_ctxh, g_wh + (size_t)3 * (Hh * Hh / 2), bo, out,
                 0, blockIdx.x, blockIdx.y, smem_g);
}

// ---------------------------------------------------------------------------
// fp16 tensor-core causal flash attention (m16n8k16), round-6 structure.
// grid: (S/64, B*NH), block 128 (4 warps, 16 q-rows each). Heavy tiles first.
// Ksh[64][36]: Q staging, then K tile (packed d-pairs).
// Vs2[32][72]: V key-pair interleaved: Vs2[kp][d] = (V[2kp][d], V[2kp+1][d]).
// Psh[64][36]: P tile (packed adjacent key-pairs).
// Static SMEM: (2304+2304+2304)*4 = 27648 bytes.
// ---------------------------------------------------------------------------
__global__ __launch_bounds__(128)
void attn_tc()
{
    __shared__ uint32_t Ksh[64][36];
    __shared__ uint32_t Vs2[32][72];
    __shared__ uint32_t Psh[64][36];

    const int tid  = threadIdx.x;
    const int lane = tid & 31;
    const int wid  = tid >> 5;      // 0..3
    const int g    = lane >> 2;     // 0..7
    const int tg   = lane & 3;      // 0..3
    const int qb   = gridDim.x - 1 - blockIdx.x;   // heavy tiles first
    const int bh   = blockIdx.y;
    const int q0   = qb * 64;
    const int R0   = wid * 16;

    const uint32_t* Qg = g_qh + (size_t)bh * Ss * (HDd/2);
    const uint32_t* Kg = g_kh + (size_t)bh * Ss * (HDd/2);
    const uint32_t* Vg = g_vh + (size_t)bh * Ss * (HDd/2);

    // ---- stage Q (fp16 packed, pre-scaled) into Ksh, pull fragments ----
    for (int u = tid; u < 64 * 8; u += 128) {
        const int r = u >> 3;
        const int c = (u & 7) * 4;
        *(uint4*)&Ksh[r][c] = *(const uint4*)&Qg[(size_t)(q0 + r) * 32 + c];
    }
    __syncthreads();

    uint32_t qf[4][4];
#pragma unroll
    for (int c = 0; c < 4; c++) {
        qf[c][0] = Ksh[R0 + g][c * 8 + tg];
        qf[c][1] = Ksh[R0 + g + 8][c * 8 + tg];
        qf[c][2] = Ksh[R0 + g][c * 8 + tg + 4];
        qf[c][3] = Ksh[R0 + g + 8][c * 8 + tg + 4];
    }

    float oacc[8][4];
#pragma unroll
    for (int nt = 0; nt < 8; nt++)
#pragma unroll
        for (int r = 0; r < 4; r++) oacc[nt][r] = 0.f;
    float m0 = -1e30f, m1 = -1e30f, l0 = 0.f, l1 = 0.f;

    for (int kb = 0; kb <= qb; kb++) {
        const int k0 = kb * 64;
        __syncthreads();   // prev tile's Ksh/Vs2/Psh reads complete

        // ---- K tile -> Ksh (uint4 copies) ----
        for (int u = tid; u < 64 * 8; u += 128) {
            const int r = u >> 3;
            const int c = (u & 7) * 4;
            *(uint4*)&Ksh[r][c] = *(const uint4*)&Kg[(size_t)(k0 + r) * 32 + c];
        }
        // ---- V tile -> Vs2 key-pair interleaved ----
        for (int u = tid; u < 512; u += 128) {
            const int kp = u >> 4;          // 0..31
            const int d4 = (u & 15) * 4;    // 0..60
            uint2 a = *(const uint2*)&Vg[(size_t)(k0 + 2*kp)     * 32 + (d4 >> 1)];
            uint2 b = *(const uint2*)&Vg[(size_t)(k0 + 2*kp + 1) * 32 + (d4 >> 1)];
            uint4 o;
            o.x = (a.x & 0xffffu) | (b.x << 16);
            o.y = (a.x >> 16)     | (b.x & 0xffff0000u);
            o.z = (a.y & 0xffffu) | (b.y << 16);
            o.w = (a.y >> 16)     | (b.y & 0xffff0000u);
            *(uint4*)&Vs2[kp][d4] = o;
        }
        __syncthreads();

        // ---- S = Q K^T (fp16, Q pre-scaled), 4 k16-chunks ----
        float sacc[8][4];
#pragma unroll
        for (int nt = 0; nt < 8; nt++)
#pragma unroll
            for (int r = 0; r < 4; r++) sacc[nt][r] = 0.f;

#pragma unroll
        for (int c = 0; c < 4; c++) {
#pragma unroll
            for (int nt = 0; nt < 8; nt++) {
                uint32_t kf[2];
                kf[0] = Ksh[nt * 8 + g][c * 8 + tg];
                kf[1] = Ksh[nt * 8 + g][c * 8 + tg + 4];
                mma_f16(sacc[nt], qf[c], kf, sacc[nt]);
            }
        }

        // ---- causal mask on diagonal tile ----
        if (kb == qb) {
            const int r0 = R0 + g;
            const int r1 = r0 + 8;
#pragma unroll
            for (int nt = 0; nt < 8; nt++) {
                const int c0 = nt * 8 + tg * 2;
                if (c0 > r0)     sacc[nt][0] = -1e30f;
                if (c0 + 1 > r0) sacc[nt][1] = -1e30f;
                if (c0 > r1)     sacc[nt][2] = -1e30f;
                if (c0 + 1 > r1) sacc[nt][3] = -1e30f;
            }
        }

        // ---- online softmax: row max ----
        float bm0 = -1e30f, bm1 = -1e30f;
#pragma unroll
        for (int nt = 0; nt < 8; nt++) {
            bm0 = fmaxf(bm0, fmaxf(sacc[nt][0], sacc[nt][1]));
            bm1 = fmaxf(bm1, fmaxf(sacc[nt][2], sacc[nt][3]));
        }
        bm0 = fmaxf(bm0, __shfl_xor_sync(0xffffffffu, bm0, 1));
        bm0 = fmaxf(bm0, __shfl_xor_sync(0xffffffffu, bm0, 2));
        bm1 = fmaxf(bm1, __shfl_xor_sync(0xffffffffu, bm1, 1));
        bm1 = fmaxf(bm1, __shfl_xor_sync(0xffffffffu, bm1, 2));

        const float nm0 = fmaxf(m0, bm0);
        const float nm1 = fmaxf(m1, bm1);
        const float c0f = __expf(m0 - nm0);
        const float c1f = __expf(m1 - nm1);
        m0 = nm0; m1 = nm1;
#pragma unroll
        for (int nt = 0; nt < 8; nt++) {
            oacc[nt][0] *= c0f; oacc[nt][1] *= c0f;
            oacc[nt][2] *= c1f; oacc[nt][3] *= c1f;
        }
        l0 *= c0f; l1 *= c1f;

        // ---- P = exp(S - m) -> Psh fp16 packed (own warp stripe) ----
        float rs0 = 0.f, rs1 = 0.f;
#pragma unroll
        for (int nt = 0; nt < 8; nt++) {
            float p0 = __expf(sacc[nt][0] - nm0);
            float p1 = __expf(sacc[nt][1] - nm0);
            float p2 = __expf(sacc[nt][2] - nm1);
            float p3 = __expf(sacc[nt][3] - nm1);
            rs0 += p0 + p1;
            rs1 += p2 + p3;
            Psh[R0 + g][nt * 4 + tg]     = packh2(p0, p1);
            Psh[R0 + g + 8][nt * 4 + tg] = packh2(p2, p3);
        }
        rs0 += __shfl_xor_sync(0xffffffffu, rs0, 1);
        rs0 += __shfl_xor_sync(0xffffffffu, rs0, 2);
        rs1 += __shfl_xor_sync(0xffffffffu, rs1, 1);
        rs1 += __shfl_xor_sync(0xffffffffu, rs1, 2);
        l0 += rs0; l1 += rs1;

        __syncwarp();      // P stripe visible within warp

        // ---- O += P @ V (fp16), 4 k16-chunks over 64 keys ----
#pragma unroll
        for (int c = 0; c < 4; c++) {
            uint32_t af[4];
            af[0] = Psh[R0 + g][c * 8 + tg];
            af[1] = Psh[R0 + g + 8][c * 8 + tg];
            af[2] = Psh[R0 + g][c * 8 + tg + 4];
            af[3] = Psh[R0 + g + 8][c * 8 + tg + 4];
#pragma unroll
            for (int nt = 0; nt < 8; nt++) {
                uint32_t bf[2];
                bf[0] = Vs2[c * 8 + tg][nt * 8 + g];
                bf[1] = Vs2[c * 8 + tg + 4][nt * 8 + g];
                mma_f16(oacc[nt], af, bf, oacc[nt]);
            }
        }
    }

    // ---- normalize + writeback ctx fp16 ----
    const float inv0 = 1.f / l0;
    const float inv1 = 1.f / l1;
    const int b    = bh / NHh;
    const int head = bh - b * NHh;
    const int s0   = q0 + R0 + g;
    const int s1   = s0 + 8;
#pragma unroll
    for (int nt = 0; nt < 8; nt++) {
        const int col = head * 64 + nt * 8 + tg * 2;
        g_ctxh[((size_t)(b * Ss) + s0) * (Hh/2) + (col >> 1)] =
            packh2(oacc[nt][0] * inv0, oacc[nt][1] * inv0);
        g_ctxh[((size_t)(b * Ss) + s1) * (Hh/2) + (col >> 1)] =
            packh2(oacc[nt][2] * inv1, oacc[nt][3] * inv1);
    }
}

// ---------------------------------------------------------------------------
// kernel_launch
// inputs: 0 hidden_states, 1 Wq, 2 bq, 3 Wk, 4 bk, 5 Wv, 6 bv, 7 Wo, 8 bo
// ---------------------------------------------------------------------------
extern "C" void kernel_launch(void* const* d_in, const int* in_sizes, int n_in,
                              void* d_out, int out_size)
{
    const float* x  = (const float*)d_in[0];
    const float* Wq = (const float*)d_in[1];
    const float* bq = (const float*)d_in[2];
    const float* Wk = (const float*)d_in[3];
    const float* bk = (const float*)d_in[4];
    const float* Wv = (const float*)d_in[5];
    const float* bv = (const float*)d_in[6];
    const float* Wo = (const float*)d_in[7];
    const float* bo = (const float*)d_in[8];
    float* out = (float*)d_out;

    cudaFuncSetAttribute(gemm_qkv, cudaFuncAttributeMaxDynamicSharedMemorySize, GEMM_SMEM);
    cudaFuncSetAttribute(gemm_out, cudaFuncAttributeMaxDynamicSharedMemorySize, GEMM_SMEM);

    preconv<<<4096, 256>>>(x, Wq, Wk, Wv, Wo);

    dim3 qkvgrid(Hh / 128, Mrows / 128, 3);   // (8, 32, 3)
    gemm_qkv<<<qkvgrid, 128, GEMM_SMEM>>>(bq, bk, bv);

    dim3 agrid(Ss / 64, Bb * NHh);            // (32, 32)
    attn_tc<<<agrid, 128>>>();

    dim3 ogrid(Hh / 128, Mrows / 128);        // (8, 32)
    gemm_out<<<ogrid, 128, GEMM_SMEM>>>(bo, out);
}

// round 11
// speedup vs baseline: 2.6411x; 1.0466x over previous
#include <cuda_runtime.h>
#include <cuda_fp16.h>
#include <cstdint>

// Problem constants
#define Bb   2
#define Ss   2048
#define Hh   1024
#define NHh  16
#define HDd  64
#define Mrows (Bb*Ss)   // 4096

// ---------------------------------------------------------------------------
// Device scratch (no allocations allowed). fp16 packed as half2 in uint32.
// ---------------------------------------------------------------------------
__device__ uint32_t g_xh[Mrows*Hh/2];        // X fp16
__device__ uint32_t g_wh[4*Hh*Hh/2];         // Wq,Wk,Wv,Wo fp16
__device__ uint32_t g_qh[Bb*NHh*Ss*HDd/2];   // Q fp16 (pre-scaled 1/8), [b,h,s,d/2]
__device__ uint32_t g_kh[Bb*NHh*Ss*HDd/2];   // K fp16
__device__ uint32_t g_vh[Bb*NHh*Ss*HDd/2];   // V fp16
__device__ uint32_t g_ctxh[Bb*Ss*Hh/2];      // attention output fp16, [b,s,h]

__device__ __forceinline__ uint32_t packh2(float a, float b) {
    __half2 h = __floats2half2_rn(a, b);
    return *(uint32_t*)&h;
}

__device__ __forceinline__ void mma_f16(float d[4], const uint32_t a[4],
                                        const uint32_t b[2], const float c[4]) {
    asm volatile(
        "mma.sync.aligned.m16n8k16.row.col.f32.f16.f16.f32 "
        "{%0,%1,%2,%3}, {%4,%5,%6,%7}, {%8,%9}, {%10,%11,%12,%13};\n"
        : "=f"(d[0]), "=f"(d[1]), "=f"(d[2]), "=f"(d[3])
        : "r"(a[0]), "r"(a[1]), "r"(a[2]), "r"(a[3]),
          "r"(b[0]), "r"(b[1]),
          "f"(c[0]), "f"(c[1]), "f"(c[2]), "f"(c[3]));
}

__device__ __forceinline__ void cp_async16(uint32_t smem_addr, const void* gptr) {
    asm volatile("cp.async.cg.shared.global [%0], [%1], 16;\n"
                 :: "r"(smem_addr), "l"(gptr));
}
__device__ __forceinline__ uint32_t s2u(const void* p) {
    return (uint32_t)__cvta_generic_to_shared(p);
}

// ---------------------------------------------------------------------------
// Prologue: convert X and the 4 weight matrices to fp16 once.
// Balanced 1D work split: items 0..NX4-1 -> X chunks, then 4x NW4 W chunks.
// ---------------------------------------------------------------------------
__global__ __launch_bounds__(256)
void preconv(const float* __restrict__ x,
             const float* __restrict__ wq, const float* __restrict__ wk,
             const float* __restrict__ wv, const float* __restrict__ wo)
{
    const int NX4 = (Mrows * Hh) / 4;   // 1,048,576
    const int NW4 = (Hh * Hh) / 4;      // 262,144
    const int i = blockIdx.x * blockDim.x + threadIdx.x;   // 0 .. NX4+4*NW4-1

    const float* src;
    uint32_t* dst;
    int j;
    if (i < NX4) {
        src = x; dst = g_xh; j = i;
    } else {
        const int w = i - NX4;
        const int z = w >> 18;          // w / NW4
        j = w & (NW4 - 1);              // w % NW4
        const float* ws[4] = {wq, wk, wv, wo};
        src = ws[z];
        dst = g_wh + (size_t)z * (Hh * Hh / 2);
    }
    float4 v = ((const float4*)src)[j];
    uint2 u;
    u.x = packh2(v.x, v.y);
    u.y = packh2(v.z, v.w);
    ((uint2*)dst)[j] = u;
}

// ---------------------------------------------------------------------------
// fp16 GEMM (m16n8k16) with cp.async 2-stage pipeline, BK=64 halves.
// 128 threads, 4 warps (2m x 2n), warp tile 64x64, CTA 128x128.
// 16 k-iterations of 4 k16-chunks each (half the barriers of BK=32).
// dst: 0 -> Yout fp32; 1/2/3 -> g_qh/kh/vh (fp16 packed).
// Dynamic SMEM: 2 stages x (A 128x36 + B 128x36) u32 = 73728 bytes.
// (Residency is register-capped at 3 CTAs/SM either way.)
// ---------------------------------------------------------------------------
#define GEMM_STG   (2*128*36)
#define GEMM_SMEM  (2*GEMM_STG*4)
#define LDAU       (Hh/2)

__device__ __forceinline__
void gemm_load_stage(const uint32_t* __restrict__ A, const uint32_t* __restrict__ Bm,
                     uint32_t* dstA, int m0, int n0, int k0u, int tid)
{
    uint32_t* dstB = dstA + 128*36;
#pragma unroll
    for (int j = 0; j < 8; j++) {
        const int id  = j * 128 + tid;     // 0..1023
        const int row = id >> 3;           // 0..127
        const int col = (id & 7) * 4;      // 0..28
        cp_async16(s2u(dstA + row*36 + col), A  + (size_t)(m0+row)*LDAU + k0u + col);
        cp_async16(s2u(dstB + row*36 + col), Bm + (size_t)(n0+row)*LDAU + k0u + col);
    }
}

__device__ __forceinline__
void gemm_tc_body(const uint32_t* __restrict__ A, const uint32_t* __restrict__ Bm,
                  const float* __restrict__ bias, float* __restrict__ Yout,
                  int dst, int bx, int by, uint32_t* smem)
{
    const int tid  = threadIdx.x;
    const int lane = tid & 31;
    const int wid  = tid >> 5;
    const int wm   = (wid & 1) * 64;
    const int wn   = (wid >> 1) * 64;
    const int m0   = by * 128;
    const int n0   = bx * 128;
    const int g    = lane >> 2;
    const int tg   = lane & 3;

    float acc[4][8][4];
#pragma unroll
    for (int mt = 0; mt < 4; mt++)
#pragma unroll
        for (int nt = 0; nt < 8; nt++)
#pragma unroll
            for (int r = 0; r < 4; r++) acc[mt][nt][r] = 0.f;

    gemm_load_stage(A, Bm, smem, m0, n0, 0, tid);
    asm volatile("cp.async.commit_group;\n");

    for (int kt = 0; kt < 16; kt++) {
        if (kt + 1 < 16) {
            gemm_load_stage(A, Bm, smem + ((kt+1)&1)*GEMM_STG, m0, n0, (kt+1)*32, tid);
            asm volatile("cp.async.commit_group;\n");
            asm volatile("cp.async.wait_group 1;\n");
        } else {
            asm volatile("cp.async.wait_group 0;\n");
        }
        __syncthreads();

        const uint32_t* As = smem + (kt & 1) * GEMM_STG;
        const uint32_t* Bs = As + 128*36;

        // BK=64 halves = 4 chunks of k16; u32 col offsets 0,8,16,24
#pragma unroll
        for (int kc8 = 0; kc8 < 32; kc8 += 8) {
            uint32_t af[4][4];
            uint32_t bf[8][2];
#pragma unroll
            for (int mt = 0; mt < 4; mt++) {
                const uint32_t* r0p = As + (wm + mt*16 + g)*36 + kc8;
                af[mt][0] = r0p[tg];
                af[mt][2] = r0p[tg + 4];
                const uint32_t* r1p = r0p + 8*36;
                af[mt][1] = r1p[tg];
                af[mt][3] = r1p[tg + 4];
            }
#pragma unroll
            for (int nt = 0; nt < 8; nt++) {
                const uint32_t* cp_ = Bs + (wn + nt*8 + g)*36 + kc8;
                bf[nt][0] = cp_[tg];
                bf[nt][1] = cp_[tg + 4];
            }
#pragma unroll
            for (int mt = 0; mt < 4; mt++)
#pragma unroll
                for (int nt = 0; nt < 8; nt++)
                    mma_f16(acc[mt][nt], af[mt], bf[nt], acc[mt][nt]);
        }
        __syncthreads();
    }

    const float qscale = (dst == 1) ? 0.125f : 1.0f;
#pragma unroll
    for (int mt = 0; mt < 4; mt++) {
#pragma unroll
        for (int nt = 0; nt < 8; nt++) {
            const int mA = m0 + wm + mt*16 + g;
            const int nA = n0 + wn + nt*8 + tg*2;
            const float b0 = bias[nA], b1 = bias[nA + 1];
#pragma unroll
            for (int half = 0; half < 2; half++) {
                const int m = mA + half * 8;
                float vx = acc[mt][nt][half*2 + 0] + b0;
                float vy = acc[mt][nt][half*2 + 1] + b1;
                if (dst == 0) {
                    float2 v; v.x = vx; v.y = vy;
                    *(float2*)&Yout[(size_t)m * Hh + nA] = v;
                } else {
                    const int bb   = m / Ss;
                    const int s    = m - bb * Ss;
                    const int head = nA >> 6;
                    const int d    = nA & 63;
                    uint32_t* dp = (dst == 1) ? g_qh : (dst == 2) ? g_kh : g_vh;
                    dp[(((size_t)(bb * NHh + head)) * Ss + s) * (HDd/2) + (d >> 1)] =
                        packh2(vx * qscale, vy * qscale);
                }
            }
        }
    }
}

__global__ __launch_bounds__(128)
void gemm_qkv(const float* __restrict__ bq, const float* __restrict__ bk,
              const float* __restrict__ bv)
{
    extern __shared__ uint32_t smem_g[];
    const int z = blockIdx.z;
    const float* bias = (z == 0) ? bq : (z == 1) ? bk : bv;
    gemm_tc_body(g_xh, g_wh + (size_t)z * (Hh * Hh / 2), bias, nullptr,
                 z + 1, blockIdx.x, blockIdx.y, smem_g);
}

__global__ __launch_bounds__(128)
void gemm_out(const float* __restrict__ bo, float* __restrict__ out)
{
    extern __shared__ uint32_t smem_g[];
    gemm_tc_body(g_ctxh, g_wh + (size_t)3 * (Hh * Hh / 2), bo, out,
                 0, blockIdx.x, blockIdx.y, smem_g);
}

// ---------------------------------------------------------------------------
// fp16 tensor-core causal flash attention (m16n8k16) — round-10 winner,
// verbatim.
// grid: (S/64, B*NH), block 128 (4 warps, 16 q-rows each). Heavy tiles first.
// Static SMEM: (2304+2304+2304)*4 = 27648 bytes.
// ---------------------------------------------------------------------------
__global__ __launch_bounds__(128)
void attn_tc()
{
    __shared__ uint32_t Ksh[64][36];
    __shared__ uint32_t Vs2[32][72];
    __shared__ uint32_t Psh[64][36];

    const int tid  = threadIdx.x;
    const int lane = tid & 31;
    const int wid  = tid >> 5;      // 0..3
    const int g    = lane >> 2;     // 0..7
    const int tg   = lane & 3;      // 0..3
    const int qb   = gridDim.x - 1 - blockIdx.x;   // heavy tiles first
    const int bh   = blockIdx.y;
    const int q0   = qb * 64;
    const int R0   = wid * 16;

    const uint32_t* Qg = g_qh + (size_t)bh * Ss * (HDd/2);
    const uint32_t* Kg = g_kh + (size_t)bh * Ss * (HDd/2);
    const uint32_t* Vg = g_vh + (size_t)bh * Ss * (HDd/2);

    // ---- stage Q (fp16 packed, pre-scaled) into Ksh, pull fragments ----
    for (int u = tid; u < 64 * 8; u += 128) {
        const int r = u >> 3;
        const int c = (u & 7) * 4;
        *(uint4*)&Ksh[r][c] = *(const uint4*)&Qg[(size_t)(q0 + r) * 32 + c];
    }
    __syncthreads();

    uint32_t qf[4][4];
#pragma unroll
    for (int c = 0; c < 4; c++) {
        qf[c][0] = Ksh[R0 + g][c * 8 + tg];
        qf[c][1] = Ksh[R0 + g + 8][c * 8 + tg];
        qf[c][2] = Ksh[R0 + g][c * 8 + tg + 4];
        qf[c][3] = Ksh[R0 + g + 8][c * 8 + tg + 4];
    }

    float oacc[8][4];
#pragma unroll
    for (int nt = 0; nt < 8; nt++)
#pragma unroll
        for (int r = 0; r < 4; r++) oacc[nt][r] = 0.f;
    float m0 = -1e30f, m1 = -1e30f, l0 = 0.f, l1 = 0.f;

    for (int kb = 0; kb <= qb; kb++) {
        const int k0 = kb * 64;
        __syncthreads();   // prev tile's Ksh/Vs2/Psh reads complete

        // ---- K tile -> Ksh (uint4 copies) ----
        for (int u = tid; u < 64 * 8; u += 128) {
            const int r = u >> 3;
            const int c = (u & 7) * 4;
            *(uint4*)&Ksh[r][c] = *(const uint4*)&Kg[(size_t)(k0 + r) * 32 + c];
        }
        // ---- V tile -> Vs2 key-pair interleaved ----
        for (int u = tid; u < 512; u += 128) {
            const int kp = u >> 4;          // 0..31
            const int d4 = (u & 15) * 4;    // 0..60
            uint2 a = *(const uint2*)&Vg[(size_t)(k0 + 2*kp)     * 32 + (d4 >> 1)];
            uint2 b = *(const uint2*)&Vg[(size_t)(k0 + 2*kp + 1) * 32 + (d4 >> 1)];
            uint4 o;
            o.x = (a.x & 0xffffu) | (b.x << 16);
            o.y = (a.x >> 16)     | (b.x & 0xffff0000u);
            o.z = (a.y & 0xffffu) | (b.y << 16);
            o.w = (a.y >> 16)     | (b.y & 0xffff0000u);
            *(uint4*)&Vs2[kp][d4] = o;
        }
        __syncthreads();

        // ---- S = Q K^T (fp16, Q pre-scaled), 4 k16-chunks ----
        float sacc[8][4];
#pragma unroll
        for (int nt = 0; nt < 8; nt++)
#pragma unroll
            for (int r = 0; r < 4; r++) sacc[nt][r] = 0.f;

#pragma unroll
        for (int c = 0; c < 4; c++) {
#pragma unroll
            for (int nt = 0; nt < 8; nt++) {
                uint32_t kf[2];
                kf[0] = Ksh[nt * 8 + g][c * 8 + tg];
                kf[1] = Ksh[nt * 8 + g][c * 8 + tg + 4];
                mma_f16(sacc[nt], qf[c], kf, sacc[nt]);
            }
        }

        // ---- causal mask on diagonal tile ----
        if (kb == qb) {
            const int r0 = R0 + g;
            const int r1 = r0 + 8;
#pragma unroll
            for (int nt = 0; nt < 8; nt++) {
                const int c0 = nt * 8 + tg * 2;
                if (c0 > r0)     sacc[nt][0] = -1e30f;
                if (c0 + 1 > r0) sacc[nt][1] = -1e30f;
                if (c0 > r1)     sacc[nt][2] = -1e30f;
                if (c0 + 1 > r1) sacc[nt][3] = -1e30f;
            }
        }

        // ---- online softmax: row max ----
        float bm0 = -1e30f, bm1 = -1e30f;
#pragma unroll
        for (int nt = 0; nt < 8; nt++) {
            bm0 = fmaxf(bm0, fmaxf(sacc[nt][0], sacc[nt][1]));
            bm1 = fmaxf(bm1, fmaxf(sacc[nt][2], sacc[nt][3]));
        }
        bm0 = fmaxf(bm0, __shfl_xor_sync(0xffffffffu, bm0, 1));
        bm0 = fmaxf(bm0, __shfl_xor_sync(0xffffffffu, bm0, 2));
        bm1 = fmaxf(bm1, __shfl_xor_sync(0xffffffffu, bm1, 1));
        bm1 = fmaxf(bm1, __shfl_xor_sync(0xffffffffu, bm1, 2));

        const float nm0 = fmaxf(m0, bm0);
        const float nm1 = fmaxf(m1, bm1);
        const float c0f = __expf(m0 - nm0);
        const float c1f = __expf(m1 - nm1);
        m0 = nm0; m1 = nm1;
#pragma unroll
        for (int nt = 0; nt < 8; nt++) {
            oacc[nt][0] *= c0f; oacc[nt][1] *= c0f;
            oacc[nt][2] *= c1f; oacc[nt][3] *= c1f;
        }
        l0 *= c0f; l1 *= c1f;

        // ---- P = exp(S - m) -> Psh fp16 packed (own warp stripe) ----
        float rs0 = 0.f, rs1 = 0.f;
#pragma unroll
        for (int nt = 0; nt < 8; nt++) {
            float p0 = __expf(sacc[nt][0] - nm0);
            float p1 = __expf(sacc[nt][1] - nm0);
            float p2 = __expf(sacc[nt][2] - nm1);
            float p3 = __expf(sacc[nt][3] - nm1);
            rs0 += p0 + p1;
            rs1 += p2 + p3;
            Psh[R0 + g][nt * 4 + tg]     = packh2(p0, p1);
            Psh[R0 + g + 8][nt * 4 + tg] = packh2(p2, p3);
        }
        rs0 += __shfl_xor_sync(0xffffffffu, rs0, 1);
        rs0 += __shfl_xor_sync(0xffffffffu, rs0, 2);
        rs1 += __shfl_xor_sync(0xffffffffu, rs1, 1);
        rs1 += __shfl_xor_sync(0xffffffffu, rs1, 2);
        l0 += rs0; l1 += rs1;

        __syncwarp();      // P stripe visible within warp

        // ---- O += P @ V (fp16), 4 k16-chunks over 64 keys ----
#pragma unroll
        for (int c = 0; c < 4; c++) {
            uint32_t af[4];
            af[0] = Psh[R0 + g][c * 8 + tg];
            af[1] = Psh[R0 + g + 8][c * 8 + tg];
            af[2] = Psh[R0 + g][c * 8 + tg + 4];
            af[3] = Psh[R0 + g + 8][c * 8 + tg + 4];
#pragma unroll
            for (int nt = 0; nt < 8; nt++) {
                uint32_t bf[2];
                bf[0] = Vs2[c * 8 + tg][nt * 8 + g];
                bf[1] = Vs2[c * 8 + tg + 4][nt * 8 + g];
                mma_f16(oacc[nt], af, bf, oacc[nt]);
            }
        }
    }

    // ---- normalize + writeback ctx fp16 ----
    const float inv0 = 1.f / l0;
    const float inv1 = 1.f / l1;
    const int b    = bh / NHh;
    const int head = bh - b * NHh;
    const int s0   = q0 + R0 + g;
    const int s1   = s0 + 8;
#pragma unroll
    for (int nt = 0; nt < 8; nt++) {
        const int col = head * 64 + nt * 8 + tg * 2;
        g_ctxh[((size_t)(b * Ss) + s0) * (Hh/2) + (col >> 1)] =
            packh2(oacc[nt][0] * inv0, oacc[nt][1] * inv0);
        g_ctxh[((size_t)(b * Ss) + s1) * (Hh/2) + (col >> 1)] =
            packh2(oacc[nt][2] * inv1, oacc[nt][3] * inv1);
    }
}

// ---------------------------------------------------------------------------
// kernel_launch
// inputs: 0 hidden_states, 1 Wq, 2 bq, 3 Wk, 4 bk, 5 Wv, 6 bv, 7 Wo, 8 bo
// ---------------------------------------------------------------------------
extern "C" void kernel_launch(void* const* d_in, const int* in_sizes, int n_in,
                              void* d_out, int out_size)
{
    const float* x  = (const float*)d_in[0];
    const float* Wq = (const float*)d_in[1];
    const float* bq = (const float*)d_in[2];
    const float* Wk = (const float*)d_in[3];
    const float* bk = (const float*)d_in[4];
    const float* Wv = (const float*)d_in[5];
    const float* bv = (const float*)d_in[6];
    const float* Wo = (const float*)d_in[7];
    const float* bo = (const float*)d_in[8];
    float* out = (float*)d_out;

    cudaFuncSetAttribute(gemm_qkv, cudaFuncAttributeMaxDynamicSharedMemorySize, GEMM_SMEM);
    cudaFuncSetAttribute(gemm_out, cudaFuncAttributeMaxDynamicSharedMemorySize, GEMM_SMEM);

    // (NX4 + 4*NW4) / 256 = (1048576 + 1048576) / 256 = 8192 blocks
    preconv<<<8192, 256>>>(x, Wq, Wk, Wv, Wo);

    dim3 qkvgrid(Hh / 128, Mrows / 128, 3);   // (8, 32, 3)
    gemm_qkv<<<qkvgrid, 128, GEMM_SMEM>>>(bq, bk, bv);

    dim3 agrid(Ss / 64, Bb * NHh);            // (32, 32)
    attn_tc<<<agrid, 128>>>();

    dim3 ogrid(Hh / 128, Mrows / 128);        // (8, 32)
    gemm_out<<<ogrid, 128, GEMM_SMEM>>>(bo, out);
}

// round 12
// speedup vs baseline: 3.2074x; 1.2144x over previous
#include <cuda_runtime.h>
#include <cuda_fp16.h>
#include <cstdint>

// Problem constants
#define Bb   2
#define Ss   2048
#define Hh   1024
#define NHh  16
#define HDd  64
#define Mrows (Bb*Ss)   // 4096

// ---------------------------------------------------------------------------
// Device scratch (no allocations allowed). fp16 packed as half2 in uint32.
// ---------------------------------------------------------------------------
__device__ uint32_t g_xh[Mrows*Hh/2];        // X fp16
__device__ uint32_t g_wh[4*Hh*Hh/2];         // Wq,Wk,Wv,Wo fp16
__device__ uint32_t g_qh[Bb*NHh*Ss*HDd/2];   // Q fp16 (pre-scaled 1/8), [b,h,s,d/2]
__device__ uint32_t g_kh[Bb*NHh*Ss*HDd/2];   // K fp16
__device__ uint32_t g_vh[Bb*NHh*Ss*HDd/2];   // V fp16
__device__ uint32_t g_ctxh[Bb*Ss*Hh/2];      // attention output fp16, [b,s,h]

__device__ __forceinline__ uint32_t packh2(float a, float b) {
    __half2 h = __floats2half2_rn(a, b);
    return *(uint32_t*)&h;
}

__device__ __forceinline__ void mma_f16(float d[4], const uint32_t a[4],
                                        const uint32_t b[2], const float c[4]) {
    asm volatile(
        "mma.sync.aligned.m16n8k16.row.col.f32.f16.f16.f32 "
        "{%0,%1,%2,%3}, {%4,%5,%6,%7}, {%8,%9}, {%10,%11,%12,%13};\n"
        : "=f"(d[0]), "=f"(d[1]), "=f"(d[2]), "=f"(d[3])
        : "r"(a[0]), "r"(a[1]), "r"(a[2]), "r"(a[3]),
          "r"(b[0]), "r"(b[1]),
          "f"(c[0]), "f"(c[1]), "f"(c[2]), "f"(c[3]));
}

__device__ __forceinline__ void cp_async16(uint32_t smem_addr, const void* gptr) {
    asm volatile("cp.async.cg.shared.global [%0], [%1], 16;\n"
                 :: "r"(smem_addr), "l"(gptr));
}
__device__ __forceinline__ uint32_t s2u(const void* p) {
    return (uint32_t)__cvta_generic_to_shared(p);
}

// ---------------------------------------------------------------------------
// Prologue: convert X and the 4 weight matrices to fp16 once (balanced 1D).
// ---------------------------------------------------------------------------
__global__ __launch_bounds__(256)
void preconv(const float* __restrict__ x,
             const float* __restrict__ wq, const float* __restrict__ wk,
             const float* __restrict__ wv, const float* __restrict__ wo)
{
    const int NX4 = (Mrows * Hh) / 4;   // 1,048,576
    const int NW4 = (Hh * Hh) / 4;      // 262,144
    const int i = blockIdx.x * blockDim.x + threadIdx.x;

    const float* src;
    uint32_t* dst;
    int j;
    if (i < NX4) {
        src = x; dst = g_xh; j = i;
    } else {
        const int w = i - NX4;
        const int z = w >> 18;
        j = w & (NW4 - 1);
        const float* ws[4] = {wq, wk, wv, wo};
        src = ws[z];
        dst = g_wh + (size_t)z * (Hh * Hh / 2);
    }
    float4 v = ((const float4*)src)[j];
    uint2 u;
    u.x = packh2(v.x, v.y);
    u.y = packh2(v.z, v.w);
    ((uint2*)dst)[j] = u;
}

// ---------------------------------------------------------------------------
// fp16 GEMM (m16n8k16) with cp.async 2-stage pipeline, BK=64 (round-11 winner).
// 128 threads, 4 warps (2m x 2n), warp tile 64x64, CTA 128x128.
// Dynamic SMEM: 2 stages x (A 128x36 + B 128x36) u32 = 73728 bytes.
// ---------------------------------------------------------------------------
#define GEMM_STG   (2*128*36)
#define GEMM_SMEM  (2*GEMM_STG*4)
#define LDAU       (Hh/2)

__device__ __forceinline__
void gemm_load_stage(const uint32_t* __restrict__ A, const uint32_t* __restrict__ Bm,
                     uint32_t* dstA, int m0, int n0, int k0u, int tid)
{
    uint32_t* dstB = dstA + 128*36;
#pragma unroll
    for (int j = 0; j < 8; j++) {
        const int id  = j * 128 + tid;
        const int row = id >> 3;
        const int col = (id & 7) * 4;
        cp_async16(s2u(dstA + row*36 + col), A  + (size_t)(m0+row)*LDAU + k0u + col);
        cp_async16(s2u(dstB + row*36 + col), Bm + (size_t)(n0+row)*LDAU + k0u + col);
    }
}

__device__ __forceinline__
void gemm_tc_body(const uint32_t* __restrict__ A, const uint32_t* __restrict__ Bm,
                  const float* __restrict__ bias, float* __restrict__ Yout,
                  int dst, int bx, int by, uint32_t* smem)
{
    const int tid  = threadIdx.x;
    const int lane = tid & 31;
    const int wid  = tid >> 5;
    const int wm   = (wid & 1) * 64;
    const int wn   = (wid >> 1) * 64;
    const int m0   = by * 128;
    const int n0   = bx * 128;
    const int g    = lane >> 2;
    const int tg   = lane & 3;

    float acc[4][8][4];
#pragma unroll
    for (int mt = 0; mt < 4; mt++)
#pragma unroll
        for (int nt = 0; nt < 8; nt++)
#pragma unroll
            for (int r = 0; r < 4; r++) acc[mt][nt][r] = 0.f;

    gemm_load_stage(A, Bm, smem, m0, n0, 0, tid);
    asm volatile("cp.async.commit_group;\n");

    for (int kt = 0; kt < 16; kt++) {
        if (kt + 1 < 16) {
            gemm_load_stage(A, Bm, smem + ((kt+1)&1)*GEMM_STG, m0, n0, (kt+1)*32, tid);
            asm volatile("cp.async.commit_group;\n");
            asm volatile("cp.async.wait_group 1;\n");
        } else {
            asm volatile("cp.async.wait_group 0;\n");
        }
        __syncthreads();

        const uint32_t* As = smem + (kt & 1) * GEMM_STG;
        const uint32_t* Bs = As + 128*36;

#pragma unroll
        for (int kc8 = 0; kc8 < 32; kc8 += 8) {
            uint32_t af[4][4];
            uint32_t bf[8][2];
#pragma unroll
            for (int mt = 0; mt < 4; mt++) {
                const uint32_t* r0p = As + (wm + mt*16 + g)*36 + kc8;
                af[mt][0] = r0p[tg];
                af[mt][2] = r0p[tg + 4];
                const uint32_t* r1p = r0p + 8*36;
                af[mt][1] = r1p[tg];
                af[mt][3] = r1p[tg + 4];
            }
#pragma unroll
            for (int nt = 0; nt < 8; nt++) {
                const uint32_t* cp_ = Bs + (wn + nt*8 + g)*36 + kc8;
                bf[nt][0] = cp_[tg];
                bf[nt][1] = cp_[tg + 4];
            }
#pragma unroll
            for (int mt = 0; mt < 4; mt++)
#pragma unroll
                for (int nt = 0; nt < 8; nt++)
                    mma_f16(acc[mt][nt], af[mt], bf[nt], acc[mt][nt]);
        }
        __syncthreads();
    }

    const float qscale = (dst == 1) ? 0.125f : 1.0f;
#pragma unroll
    for (int mt = 0; mt < 4; mt++) {
#pragma unroll
        for (int nt = 0; nt < 8; nt++) {
            const int mA = m0 + wm + mt*16 + g;
            const int nA = n0 + wn + nt*8 + tg*2;
            const float b0 = bias[nA], b1 = bias[nA + 1];
#pragma unroll
            for (int half = 0; half < 2; half++) {
                const int m = mA + half * 8;
                float vx = acc[mt][nt][half*2 + 0] + b0;
                float vy = acc[mt][nt][half*2 + 1] + b1;
                if (dst == 0) {
                    float2 v; v.x = vx; v.y = vy;
                    *(float2*)&Yout[(size_t)m * Hh + nA] = v;
                } else {
                    const int bb   = m / Ss;
                    const int s    = m - bb * Ss;
                    const int head = nA >> 6;
                    const int d    = nA & 63;
                    uint32_t* dp = (dst == 1) ? g_qh : (dst == 2) ? g_kh : g_vh;
                    dp[(((size_t)(bb * NHh + head)) * Ss + s) * (HDd/2) + (d >> 1)] =
                        packh2(vx * qscale, vy * qscale);
                }
            }
        }
    }
}

__global__ __launch_bounds__(128)
void gemm_qkv(const float* __restrict__ bq, const float* __restrict__ bk,
              const float* __restrict__ bv)
{
    extern __shared__ uint32_t smem_g[];
    const int z = blockIdx.z;
    const float* bias = (z == 0) ? bq : (z == 1) ? bk : bv;
    gemm_tc_body(g_xh, g_wh + (size_t)z * (Hh * Hh / 2), bias, nullptr,
                 z + 1, blockIdx.x, blockIdx.y, smem_g);
}

__global__ __launch_bounds__(128)
void gemm_out(const float* __restrict__ bo, float* __restrict__ out)
{
    extern __shared__ uint32_t smem_g[];
    gemm_tc_body(g_ctxh, g_wh + (size_t)3 * (Hh * Hh / 2), bo, out,
                 0, blockIdx.x, blockIdx.y, smem_g);
}

// ---------------------------------------------------------------------------
// fp16 tensor-core causal flash attention (m16n8k16), v7:
// round-10 structure + register-staged software pipeline for K/V tile loads
// (LDGs for tile kb+1 issued before computing tile kb -> latency overlapped).
// grid: (S/64, B*NH), block 128 (4 warps, 16 q-rows each). Heavy tiles first.
// Static SMEM: (2304+2304+2304)*4 = 27648 bytes.
// ---------------------------------------------------------------------------
__global__ __launch_bounds__(128)
void attn_tc()
{
    __shared__ uint32_t Ksh[64][36];
    __shared__ uint32_t Vs2[32][72];
    __shared__ uint32_t Psh[64][36];

    const int tid  = threadIdx.x;
    const int lane = tid & 31;
    const int wid  = tid >> 5;      // 0..3
    const int g    = lane >> 2;     // 0..7
    const int tg   = lane & 3;      // 0..3
    const int qb   = gridDim.x - 1 - blockIdx.x;   // heavy tiles first
    const int bh   = blockIdx.y;
    const int q0   = qb * 64;
    const int R0   = wid * 16;

    const uint32_t* Qg = g_qh + (size_t)bh * Ss * (HDd/2);
    const uint32_t* Kg = g_kh + (size_t)bh * Ss * (HDd/2);
    const uint32_t* Vg = g_vh + (size_t)bh * Ss * (HDd/2);

    // loop-invariant loader coordinates (4 chunks per thread)
    int kr_[4], kc_[4], vkp_[4], vd4_[4];
#pragma unroll
    for (int j = 0; j < 4; j++) {
        const int id = j * 128 + tid;      // 0..511
        kr_[j]  = id >> 3;                 // K row 0..63
        kc_[j]  = (id & 7) * 4;            // K u32 col 0..28
        vkp_[j] = id >> 4;                 // V key-pair 0..31
        vd4_[j] = (id & 15) * 4;           // V u32 col 0..60
    }

    // ---- stage Q (fp16 packed, pre-scaled) into Ksh, pull fragments ----
    for (int u = tid; u < 64 * 8; u += 128) {
        const int r = u >> 3;
        const int c = (u & 7) * 4;
        *(uint4*)&Ksh[r][c] = *(const uint4*)&Qg[(size_t)(q0 + r) * 32 + c];
    }
    __syncthreads();

    uint32_t qf[4][4];
#pragma unroll
    for (int c = 0; c < 4; c++) {
        qf[c][0] = Ksh[R0 + g][c * 8 + tg];
        qf[c][1] = Ksh[R0 + g + 8][c * 8 + tg];
        qf[c][2] = Ksh[R0 + g][c * 8 + tg + 4];
        qf[c][3] = Ksh[R0 + g + 8][c * 8 + tg + 4];
    }

    // ---- prefetch tile 0 into registers ----
    uint4 kreg[4];
    uint2 vra[4], vrb[4];
#pragma unroll
    for (int j = 0; j < 4; j++) {
        kreg[j] = *(const uint4*)&Kg[(size_t)kr_[j] * 32 + kc_[j]];
        vra[j]  = *(const uint2*)&Vg[(size_t)(2*vkp_[j])     * 32 + (vd4_[j] >> 1)];
        vrb[j]  = *(const uint2*)&Vg[(size_t)(2*vkp_[j] + 1) * 32 + (vd4_[j] >> 1)];
    }

    float oacc[8][4];
#pragma unroll
    for (int nt = 0; nt < 8; nt++)
#pragma unroll
        for (int r = 0; r < 4; r++) oacc[nt][r] = 0.f;
    float m0 = -1e30f, m1 = -1e30f, l0 = 0.f, l1 = 0.f;

    for (int kb = 0; kb <= qb; kb++) {
        __syncthreads();   // prev tile's Ksh/Vs2/Psh reads complete (and qf extract, kb=0)

        // ---- store staged registers to SMEM (K direct, V interleaved) ----
#pragma unroll
        for (int j = 0; j < 4; j++) {
            *(uint4*)&Ksh[kr_[j]][kc_[j]] = kreg[j];
            uint4 o;
            o.x = (vra[j].x & 0xffffu) | (vrb[j].x << 16);
            o.y = (vra[j].x >> 16)     | (vrb[j].x & 0xffff0000u);
            o.z = (vra[j].y & 0xffffu) | (vrb[j].y << 16);
            o.w = (vra[j].y >> 16)     | (vrb[j].y & 0xffff0000u);
            *(uint4*)&Vs2[vkp_[j]][vd4_[j]] = o;
        }
        __syncthreads();

        // ---- issue loads for next tile (overlaps with compute below) ----
        if (kb < qb) {
            const int k0n = (kb + 1) * 64;
#pragma unroll
            for (int j = 0; j < 4; j++) {
                kreg[j] = *(const uint4*)&Kg[(size_t)(k0n + kr_[j]) * 32 + kc_[j]];
                vra[j]  = *(const uint2*)&Vg[(size_t)(k0n + 2*vkp_[j])     * 32 + (vd4_[j] >> 1)];
                vrb[j]  = *(const uint2*)&Vg[(size_t)(k0n + 2*vkp_[j] + 1) * 32 + (vd4_[j] >> 1)];
            }
        }

        // ---- S = Q K^T (fp16, Q pre-scaled), 4 k16-chunks ----
        float sacc[8][4];
#pragma unroll
        for (int nt = 0; nt < 8; nt++)
#pragma unroll
            for (int r = 0; r < 4; r++) sacc[nt][r] = 0.f;

#pragma unroll
        for (int c = 0; c < 4; c++) {
#pragma unroll
            for (int nt = 0; nt < 8; nt++) {
                uint32_t kf[2];
                kf[0] = Ksh[nt * 8 + g][c * 8 + tg];
                kf[1] = Ksh[nt * 8 + g][c * 8 + tg + 4];
                mma_f16(sacc[nt], qf[c], kf, sacc[nt]);
            }
        }

        // ---- causal mask on diagonal tile ----
        if (kb == qb) {
            const int r0 = R0 + g;
            const int r1 = r0 + 8;
#pragma unroll
            for (int nt = 0; nt < 8; nt++) {
                const int c0 = nt * 8 + tg * 2;
                if (c0 > r0)     sacc[nt][0] = -1e30f;
                if (c0 + 1 > r0) sacc[nt][1] = -1e30f;
                if (c0 > r1)     sacc[nt][2] = -1e30f;
                if (c0 + 1 > r1) sacc[nt][3] = -1e30f;
            }
        }

        // ---- online softmax: row max ----
        float bm0 = -1e30f, bm1 = -1e30f;
#pragma unroll
        for (int nt = 0; nt < 8; nt++) {
            bm0 = fmaxf(bm0, fmaxf(sacc[nt][0], sacc[nt][1]));
            bm1 = fmaxf(bm1, fmaxf(sacc[nt][2], sacc[nt][3]));
        }
        bm0 = fmaxf(bm0, __shfl_xor_sync(0xffffffffu, bm0, 1));
        bm0 = fmaxf(bm0, __shfl_xor_sync(0xffffffffu, bm0, 2));
        bm1 = fmaxf(bm1, __shfl_xor_sync(0xffffffffu, bm1, 1));
        bm1 = fmaxf(bm1, __shfl_xor_sync(0xffffffffu, bm1, 2));

        const float nm0 = fmaxf(m0, bm0);
        const float nm1 = fmaxf(m1, bm1);
        const float c0f = __expf(m0 - nm0);
        const float c1f = __expf(m1 - nm1);
        m0 = nm0; m1 = nm1;
#pragma unroll
        for (int nt = 0; nt < 8; nt++) {
            oacc[nt][0] *= c0f; oacc[nt][1] *= c0f;
            oacc[nt][2] *= c1f; oacc[nt][3] *= c1f;
        }
        l0 *= c0f; l1 *= c1f;

        // ---- P = exp(S - m) -> Psh fp16 packed (own warp stripe) ----
        float rs0 = 0.f, rs1 = 0.f;
#pragma unroll
        for (int nt = 0; nt < 8; nt++) {
            float p0 = __expf(sacc[nt][0] - nm0);
            float p1 = __expf(sacc[nt][1] - nm0);
            float p2 = __expf(sacc[nt][2] - nm1);
            float p3 = __expf(sacc[nt][3] - nm1);
            rs0 += p0 + p1;
            rs1 += p2 + p3;
            Psh[R0 + g][nt * 4 + tg]     = packh2(p0, p1);
            Psh[R0 + g + 8][nt * 4 + tg] = packh2(p2, p3);
        }
        rs0 += __shfl_xor_sync(0xffffffffu, rs0, 1);
        rs0 += __shfl_xor_sync(0xffffffffu, rs0, 2);
        rs1 += __shfl_xor_sync(0xffffffffu, rs1, 1);
        rs1 += __shfl_xor_sync(0xffffffffu, rs1, 2);
        l0 += rs0; l1 += rs1;

        __syncwarp();      // P stripe visible within warp

        // ---- O += P @ V (fp16), 4 k16-chunks over 64 keys ----
#pragma unroll
        for (int c = 0; c < 4; c++) {
            uint32_t af[4];
            af[0] = Psh[R0 + g][c * 8 + tg];
            af[1] = Psh[R0 + g + 8][c * 8 + tg];
            af[2] = Psh[R0 + g][c * 8 + tg + 4];
            af[3] = Psh[R0 + g + 8][c * 8 + tg + 4];
#pragma unroll
            for (int nt = 0; nt < 8; nt++) {
                uint32_t bf[2];
                bf[0] = Vs2[c * 8 + tg][nt * 8 + g];
                bf[1] = Vs2[c * 8 + tg + 4][nt * 8 + g];
                mma_f16(oacc[nt], af, bf, oacc[nt]);
            }
        }
    }

    // ---- normalize + writeback ctx fp16 ----
    const float inv0 = 1.f / l0;
    const float inv1 = 1.f / l1;
    const int b    = bh / NHh;
    const int head = bh - b * NHh;
    const int s0   = q0 + R0 + g;
    const int s1   = s0 + 8;
#pragma unroll
    for (int nt = 0; nt < 8; nt++) {
        const int col = head * 64 + nt * 8 + tg * 2;
        g_ctxh[((size_t)(b * Ss) + s0) * (Hh/2) + (col >> 1)] =
            packh2(oacc[nt][0] * inv0, oacc[nt][1] * inv0);
        g_ctxh[((size_t)(b * Ss) + s1) * (Hh/2) + (col >> 1)] =
            packh2(oacc[nt][2] * inv1, oacc[nt][3] * inv1);
    }
}

// ---------------------------------------------------------------------------
// kernel_launch
// inputs: 0 hidden_states, 1 Wq, 2 bq, 3 Wk, 4 bk, 5 Wv, 6 bv, 7 Wo, 8 bo
// ---------------------------------------------------------------------------
extern "C" void kernel_launch(void* const* d_in, const int* in_sizes, int n_in,
                              void* d_out, int out_size)
{
    const float* x  = (const float*)d_in[0];
    const float* Wq = (const float*)d_in[1];
    const float* bq = (const float*)d_in[2];
    const float* Wk = (const float*)d_in[3];
    const float* bk = (const float*)d_in[4];
    const float* Wv = (const float*)d_in[5];
    const float* bv = (const float*)d_in[6];
    const float* Wo = (const float*)d_in[7];
    const float* bo = (const float*)d_in[8];
    float* out = (float*)d_out;

    cudaFuncSetAttribute(gemm_qkv, cudaFuncAttributeMaxDynamicSharedMemorySize, GEMM_SMEM);
    cudaFuncSetAttribute(gemm_out, cudaFuncAttributeMaxDynamicSharedMemorySize, GEMM_SMEM);

    preconv<<<8192, 256>>>(x, Wq, Wk, Wv, Wo);

    dim3 qkvgrid(Hh / 128, Mrows / 128, 3);   // (8, 32, 3)
    gemm_qkv<<<qkvgrid, 128, GEMM_SMEM>>>(bq, bk, bv);

    dim3 agrid(Ss / 64, Bb * NHh);            // (32, 32)
    attn_tc<<<agrid, 128>>>();

    dim3 ogrid(Hh / 128, Mrows / 128);        // (8, 32)
    gemm_out<<<ogrid, 128, GEMM_SMEM>>>(bo, out);
}